// round 8
// baseline (speedup 1.0000x reference)
#include <cuda_runtime.h>
#include <math.h>
#include <float.h>
#include <limits.h>

#define BB 32
#define TT 50
#define DD 100
#define NBRN 6
#define SPQ 4
#define TS 49
#define RK 10
#define NINF (-INFINITY)

// ---------------- scratch (__device__ globals) ----------------
__device__ __align__(16) float g_WT_agg[3][DD * DD];   // [j][k*100+o] = agg_w[j][o][k]
__device__ __align__(16) float g_WT_last[DD * DD];     // [k*100+o]
__device__ __align__(16) float g_WT_fus[2 * DD * DD];  // [k*100+o]
__device__ __align__(16) float g_WT_ih[DD * 4 * DD];   // [k*400+o4]
__device__ __align__(16) float g_Whh4[DD * DD * 4];    // [(k*100+o)*4 + gate]
__device__ __align__(16) float g_qv[DD];
__device__ __align__(16) float g_kv[DD];
__device__ float g_scal[4];                            // qb, kb, bw
__device__ __align__(16) float g_pre[TS * BB * 4 * DD];
__device__ __align__(16) float g_qs[TS * BB * 5 * DD];
__device__ float g_ql[TS * BB * 5];
__device__ int   g_idx[TS * BB * RK];
__device__ int   g_sval[TS * BB * 11];

// ---------------- prep ----------------
__global__ void prep_kernel(const float* __restrict__ agg_w,
                            const float* __restrict__ W_agg_last,
                            const float* __restrict__ W_fusion,
                            const float* __restrict__ W_ih,
                            const float* __restrict__ W_hh,
                            const float* __restrict__ W_query,
                            const float* __restrict__ b_query,
                            const float* __restrict__ W_key,
                            const float* __restrict__ b_key,
                            const float* __restrict__ W_w,
                            const float* __restrict__ b_w)
{
    int tid = blockIdx.x * blockDim.x + threadIdx.x;
    int nt = gridDim.x * blockDim.x;
    for (int i = tid; i < 3 * DD * DD; i += nt) {
        int j = i / (DD * DD), rem = i % (DD * DD);
        int o = rem / DD, k = rem % DD;
        g_WT_agg[j][k * DD + o] = agg_w[i];
    }
    for (int i = tid; i < DD * DD; i += nt) {
        int o = i / DD, k = i % DD;
        g_WT_last[k * DD + o] = W_agg_last[i];
    }
    for (int i = tid; i < DD * 2 * DD; i += nt) {
        int o = i / (2 * DD), k = i % (2 * DD);
        g_WT_fus[k * DD + o] = W_fusion[i];
    }
    for (int i = tid; i < 4 * DD * DD; i += nt) {
        int o4 = i / DD, k = i % DD;
        g_WT_ih[k * 4 * DD + o4] = W_ih[i];
    }
    for (int i = tid; i < 4 * DD * DD; i += nt) {
        int o4 = i / DD, k = i % DD;
        int g = o4 / DD, o = o4 % DD;
        g_Whh4[(k * DD + o) * 4 + g] = W_hh[i];
    }
    for (int k = tid; k < DD; k += nt) {
        float a = 0.f, bs = 0.f;
        for (int o = 0; o < DD; o++) {
            a  += W_query[o * DD + k] * W_w[o];
            bs += W_key[o * DD + k] * W_w[DD + o];
        }
        g_qv[k] = a;
        g_kv[k] = bs;
    }
    if (tid == 0) {
        float qb = 0.f, kb = 0.f;
        for (int o = 0; o < DD; o++) {
            qb += b_query[o] * W_w[o];
            kb += b_key[o] * W_w[DD + o];
        }
        g_scal[0] = qb; g_scal[1] = kb; g_scal[2] = b_w[0];
    }
}

// tiled matvec: sOut[r][tid] = act(bias[tid] + sum_k sIn[r][k]*WT[k][tid])
// ACT: 0 = tanh, 1 = relu
template <int TR, int KK, int ACT>
__device__ __forceinline__ void mv_tile(const float* __restrict__ WT,
                                        const float* __restrict__ bias,
                                        const float* __restrict__ sIn,
                                        float* __restrict__ sOut, int tid)
{
    if (tid < DD) {
        float acc[TR];
#pragma unroll
        for (int r = 0; r < TR; r++) acc[r] = 0.f;
#pragma unroll 1
        for (int k = 0; k < KK; k += 4) {
            float w0 = WT[(k + 0) * DD + tid];
            float w1 = WT[(k + 1) * DD + tid];
            float w2 = WT[(k + 2) * DD + tid];
            float w3 = WT[(k + 3) * DD + tid];
#pragma unroll
            for (int r = 0; r < TR; r++) {
                const float4 s4 = *reinterpret_cast<const float4*>(sIn + r * KK + k);
                acc[r] = fmaf(s4.x, w0, acc[r]);
                acc[r] = fmaf(s4.y, w1, acc[r]);
                acc[r] = fmaf(s4.z, w2, acc[r]);
                acc[r] = fmaf(s4.w, w3, acc[r]);
            }
        }
        float bv = bias[tid];
#pragma unroll
        for (int r = 0; r < TR; r++) {
            float v = acc[r] + bv;
            sOut[r * DD + tid] = (ACT == 0) ? tanhf(v) : fmaxf(v, 0.f);
        }
    }
}

// ---------------- Phase A ----------------
__global__ __launch_bounds__(128) void phaseA_kernel(
    const int* __restrict__ user, const int* __restrict__ question,
    const int* __restrict__ response, const int* __restrict__ mask,
    const int* __restrict__ q_neighbors, const int* __restrict__ s_neighbors,
    const int* __restrict__ u_neighbors, const int* __restrict__ q_neighbors_2,
    const int* __restrict__ qs_index,
    const float* __restrict__ emb_question, const float* __restrict__ emb_question_2,
    const float* __restrict__ emb_skill, const float* __restrict__ emb_user,
    const float* __restrict__ emb_response,
    const float* __restrict__ w1_q, const float* __restrict__ w2_q,
    const float* __restrict__ b_ih, const float* __restrict__ b_hh,
    const float* __restrict__ agg_b, const float* __restrict__ b_agg_last,
    const float* __restrict__ b_fusion)
{
    __shared__ int l1[NBRN];
    __shared__ int l2[36];
    __shared__ int l3[216];
    __shared__ __align__(16) float s2[36 * DD];
    __shared__ __align__(16) float e2[36 * DD];
    __shared__ __align__(16) float s1[6 * DD];
    __shared__ __align__(16) float e1[6 * DD];
    __shared__ __align__(16) float s0[DD];
    __shared__ __align__(16) float e0v[DD];
    __shared__ __align__(16) float ehat[DD];
    __shared__ __align__(16) float xf[2 * DD];
    __shared__ __align__(16) float etv[DD];
    __shared__ __align__(16) float qs_s[5 * DD];
    __shared__ float scores[TT];

    const int unit = blockIdx.x;
    const int t = unit / BB;
    const int b = unit % BB;
    const int tid = threadIdx.x;

    const int q_t = question[b * TT + t];
    const int u_t = user[b * TT + t];
    const int r_t = response[b * TT + t];
    const int m = mask[b * TT + t];
    const float w1 = w1_q[0], w2 = w2_q[0];
    const float inv6 = 1.0f / 6.0f;

    if (m) {
        for (int side = 0; side < 2; side++) {
            int node;
            const int *tabA, *tabB;
            const float *embX, *embY;
            if (side == 0) {
                node = q_t; tabA = q_neighbors; tabB = s_neighbors;
                embX = emb_question; embY = emb_skill;
            } else {
                node = u_t; tabA = u_neighbors; tabB = q_neighbors_2;
                embX = emb_user; embY = emb_question_2;
            }
            if (tid < NBRN) l1[tid] = tabA[node * NBRN + tid];
            __syncthreads();
            if (tid < 36) l2[tid] = tabB[l1[tid / 6] * NBRN + tid % 6];
            __syncthreads();
            for (int i = tid; i < 216; i += blockDim.x)
                l3[i] = tabA[l2[i / 6] * NBRN + i % 6];
            __syncthreads();
            if (tid < DD) {
                const int k = tid;
                {
                    float mm = 0.f;
#pragma unroll
                    for (int i = 0; i < 6; i++) mm += embY[l1[i] * DD + k];
                    s0[k] = embX[node * DD + k] + mm * inv6;
                }
                for (int i = 0; i < 6; i++) {
                    float mm = 0.f;
#pragma unroll
                    for (int j = 0; j < 6; j++) mm += embX[l2[i * 6 + j] * DD + k];
                    s1[i * DD + k] = embY[l1[i] * DD + k] + mm * inv6;
                }
                for (int p = 0; p < 36; p++) {
                    float mm = 0.f;
#pragma unroll
                    for (int l = 0; l < 6; l++) mm += embY[l3[p * 6 + l] * DD + k];
                    s2[p * DD + k] = embX[l2[p] * DD + k] + mm * inv6;
                }
            }
            __syncthreads();
            // sweep i=0 (all s-vectors built from pre-sweep values)
            mv_tile<18, DD, 0>(g_WT_agg[2], agg_b + 2 * DD, s2, e2, tid);
            mv_tile<18, DD, 0>(g_WT_agg[2], agg_b + 2 * DD, s2 + 18 * DD, e2 + 18 * DD, tid);
            mv_tile<6, DD, 0>(g_WT_agg[1], agg_b + 1 * DD, s1, e1, tid);
            mv_tile<1, DD, 0>(g_WT_agg[0], agg_b + 0 * DD, s0, e0v, tid);
            __syncthreads();
            // sweep i=1
            if (tid < DD) {
                const int k = tid;
                float nm[6];
                for (int i = 0; i < 6; i++) {
                    float mm = 0.f;
#pragma unroll
                    for (int j = 0; j < 6; j++) mm += e2[(i * 6 + j) * DD + k];
                    nm[i] = e1[i * DD + k] + mm * inv6;
                }
                float mm = 0.f;
#pragma unroll
                for (int i = 0; i < 6; i++) mm += e1[i * DD + k];
                s0[k] = e0v[k] + mm * inv6;
                for (int i = 0; i < 6; i++) s1[i * DD + k] = nm[i];
            }
            __syncthreads();
            mv_tile<6, DD, 0>(g_WT_agg[1], agg_b + 1 * DD, s1, e1, tid);
            mv_tile<1, DD, 0>(g_WT_agg[0], agg_b + 0 * DD, s0, e0v, tid);
            __syncthreads();
            // sweep i=2
            if (tid < DD) {
                const int k = tid;
                float mm = 0.f;
#pragma unroll
                for (int i = 0; i < 6; i++) mm += e1[i * DD + k];
                s0[k] = e0v[k] + mm * inv6;
            }
            __syncthreads();
            mv_tile<1, DD, 0>(g_WT_agg[0], agg_b + 0 * DD, s0, e0v, tid);
            __syncthreads();
            mv_tile<1, DD, 0>(g_WT_last, b_agg_last, e0v, s0, tid);
            __syncthreads();
            if (tid < DD) {
                if (side == 0) ehat[tid] = w1 * s0[tid];
                else ehat[tid] += w2 * s0[tid];
            }
            __syncthreads();
        }
    } else {
        if (tid < DD)
            ehat[tid] = w1 * emb_question[q_t * DD + tid] + w2 * emb_question_2[q_t * DD + tid];
        __syncthreads();
    }

    // fusion
    if (tid < DD) {
        xf[tid] = ehat[tid];
        xf[DD + tid] = emb_response[r_t * DD + tid];
    }
    __syncthreads();
    mv_tile<1, 2 * DD, 1>(g_WT_fus, b_fusion, xf, etv, tid);
    __syncthreads();

    // pre = e_t @ W_ih^T + b_ih + b_hh
    for (int o4 = tid; o4 < 4 * DD; o4 += blockDim.x) {
        float acc = b_ih[o4] + b_hh[o4];
        for (int k = 0; k < DD; k += 4) {
            const float4 s4 = *reinterpret_cast<const float4*>(etv + k);
            acc = fmaf(s4.x, g_WT_ih[(k + 0) * 4 * DD + o4], acc);
            acc = fmaf(s4.y, g_WT_ih[(k + 1) * 4 * DD + o4], acc);
            acc = fmaf(s4.z, g_WT_ih[(k + 2) * 4 * DD + o4], acc);
            acc = fmaf(s4.w, g_WT_ih[(k + 3) * 4 * DD + o4], acc);
        }
        g_pre[(t * BB + b) * 4 * DD + o4] = acc;
    }

    // attention precompute
    const int qn = question[b * TT + t + 1];
    if (tid < DD) {
        const int k = tid;
        float v = emb_question[qn * DD + k];
        qs_s[k] = v;
        g_qs[(size_t)((t * BB + b) * 5) * DD + k] = v;
#pragma unroll
        for (int j = 0; j < 4; j++) {
            int sidx = qs_index[qn * SPQ + j];
            v = emb_skill[sidx * DD + k];
            qs_s[(1 + j) * DD + k] = v;
            g_qs[(size_t)((t * BB + b) * 5 + 1 + j) * DD + k] = v;
        }
    }
    __syncthreads();
    if (tid < 5) {
        float acc = g_scal[0];
        for (int k = 0; k < DD; k++) acc += qs_s[tid * DD + k] * g_qv[k];
        g_ql[(t * BB + b) * 5 + tid] = acc;
    }
    if (tid < TT) {
        const int tp = tid;
        float sc = NINF;
        if (tp < t) {
            const int qq = question[b * TT + tp];
            float acc = 0.f;
            for (int k = 0; k < DD; k++) acc += emb_question[qq * DD + k] * qs_s[k];
            sc = acc;
        }
        scores[tp] = sc;
    }
    __syncthreads();
    // top-10 (warp 0), lax.top_k semantics: values desc, lower index first on
    // ties. Taken entries get index=INT_MAX so tied NINF entries are selected
    // in strictly ascending index order without repeats.
    if (tid < 32) {
        float v0 = (tid < TT) ? scores[tid] : NINF;
        float v1 = (tid + 32 < TT) ? scores[tid + 32] : NINF;
        int idx0 = (tid < TT) ? tid : INT_MAX;
        int idx1 = (tid + 32 < TT) ? (tid + 32) : INT_MAX;
        for (int r = 0; r < RK; r++) {
            float bv; int bi;
            if (v1 > v0 || (v1 == v0 && idx1 < idx0)) { bv = v1; bi = idx1; }
            else { bv = v0; bi = idx0; }
#pragma unroll
            for (int off = 16; off; off >>= 1) {
                float ov = __shfl_xor_sync(0xffffffffu, bv, off);
                int oi = __shfl_xor_sync(0xffffffffu, bi, off);
                if (ov > bv || (ov == bv && oi < bi)) { bv = ov; bi = oi; }
            }
            if (tid == 0) {
                g_idx[(t * BB + b) * RK + r] = bi;
                g_sval[(t * BB + b) * 11 + 1 + r] = (bi < t) ? 1 : 0;
            }
            if (idx0 == bi) { v0 = NINF; idx0 = INT_MAX; }
            if (idx1 == bi) { v1 = NINF; idx1 = INT_MAX; }
        }
        if (tid == 0) g_sval[(t * BB + b) * 11 + 0] = 1;
    }
}

// ---------------- Phase B: per-batch-row LSTM + attention ----------------
__global__ __launch_bounds__(256) void phaseB_kernel(const int* __restrict__ mask,
                                                     float* __restrict__ out)
{
    __shared__ __align__(16) float h[DD];
    __shared__ __align__(16) float cstate[DD];
    __shared__ __align__(16) float sh[TT * DD];
    __shared__ float dots[66];
    __shared__ int idx_s[RK];
    __shared__ int sval_s[11];
    __shared__ float ql_s[5];

    const int b = blockIdx.x;
    const int tid = threadIdx.x;
    const int nw = blockDim.x / 32;

    for (int i = tid; i < TT * DD; i += blockDim.x) sh[i] = 0.f;
    if (tid < DD) { h[tid] = 0.f; cstate[tid] = 0.f; }
    if (tid == 0) out[b * TT + 0] = 0.5f;
    __syncthreads();

    for (int t = 0; t < TS; t++) {
        // small per-step loads by threads not in the gate path
        if (tid >= 128 && tid < 128 + RK) idx_s[tid - 128] = g_idx[(t * BB + b) * RK + (tid - 128)];
        if (tid >= 160 && tid < 160 + 11) sval_s[tid - 160] = g_sval[(t * BB + b) * 11 + (tid - 160)];
        if (tid >= 192 && tid < 192 + 5) ql_s[tid - 192] = g_ql[(t * BB + b) * 5 + (tid - 192)];

        const int m = mask[b * TT + t];
        float hnew = 0.f, cnew = 0.f;
        if (tid < DD) {
            const int o = tid;
            const float* pre = &g_pre[(size_t)(t * BB + b) * 4 * DD];
            float a0 = pre[o], a1 = pre[DD + o], a2 = pre[2 * DD + o], a3 = pre[3 * DD + o];
#pragma unroll 4
            for (int k = 0; k < DD; k++) {
                const float hk = h[k];
                const float4 w = reinterpret_cast<const float4*>(g_Whh4)[k * DD + o];
                a0 = fmaf(hk, w.x, a0);
                a1 = fmaf(hk, w.y, a1);
                a2 = fmaf(hk, w.z, a2);
                a3 = fmaf(hk, w.w, a3);
            }
            const float ig = 1.f / (1.f + expf(-a0));
            const float fg = 1.f / (1.f + expf(-a1));
            const float gg = tanhf(a2);
            const float og = 1.f / (1.f + expf(-a3));
            const float c2 = fg * cstate[o] + ig * gg;
            const float h2 = og * tanhf(c2);
            hnew = m ? h2 : h[o];
            cnew = m ? c2 : cstate[o];
        }
        __syncthreads();   // all reads of old h done
        if (tid < DD) {
            h[tid] = hnew;
            cstate[tid] = cnew;
            sh[t * DD + tid] = hnew;
        }
        __syncthreads();

        // 66 dots: d<55 -> g[q][s]; d>=55 -> states[s]·kv
        const int wid = tid / 32, lane = tid % 32;
        for (int d = wid; d < 66; d += nw) {
            const float* av;
            const float* bv;
            if (d < 55) {
                const int q = d / 11, s = d % 11;
                av = &g_qs[(size_t)((t * BB + b) * 5 + q) * DD];
                bv = (s == 0) ? h : &sh[idx_s[s - 1] * DD];
            } else {
                const int s = d - 55;
                av = g_kv;
                bv = (s == 0) ? h : &sh[idx_s[s - 1] * DD];
            }
            float acc = av[lane] * bv[lane] + av[lane + 32] * bv[lane + 32]
                      + av[lane + 64] * bv[lane + 64];
            if (lane < 4) acc += av[lane + 96] * bv[lane + 96];
#pragma unroll
            for (int off = 16; off; off >>= 1)
                acc += __shfl_xor_sync(0xffffffffu, acc, off);
            if (lane == 0) dots[d] = acc;
        }
        __syncthreads();

        // softmax over 55 logits + weighted sum -> sigmoid (warp 0)
        if (tid < 32) {
            const float kbbw = g_scal[1] + g_scal[2];
            const int j0 = tid, j1 = tid + 32;
            float l0 = NINF, l1v = NINF, g0 = 0.f, g1 = 0.f;
            if (j0 < 55) {
                const int q = j0 / 11, s = j0 % 11;
                if (sval_s[s]) l0 = ql_s[q] + dots[55 + s] + kbbw;
                g0 = dots[j0];
            }
            if (j1 < 55) {
                const int q = j1 / 11, s = j1 % 11;
                if (sval_s[s]) l1v = ql_s[q] + dots[55 + s] + kbbw;
                g1 = dots[j1];
            }
            float mx = fmaxf(l0, l1v);
#pragma unroll
            for (int off = 16; off; off >>= 1)
                mx = fmaxf(mx, __shfl_xor_sync(0xffffffffu, mx, off));
            float e0 = (l0 == NINF) ? 0.f : expf(l0 - mx);
            float e1 = (l1v == NINF) ? 0.f : expf(l1v - mx);
            float es = e0 + e1;
            float ws = e0 * g0 + e1 * g1;
#pragma unroll
            for (int off = 16; off; off >>= 1) {
                es += __shfl_xor_sync(0xffffffffu, es, off);
                ws += __shfl_xor_sync(0xffffffffu, ws, off);
            }
            if (tid == 0) {
                const float y = 1.f / (1.f + expf(-(ws / es)));
                out[b * TT + t + 1] = y;
            }
        }
        __syncthreads();   // protect dots/idx_s/sval_s/ql_s before next step
    }
}

extern "C" void kernel_launch(void* const* d_in, const int* in_sizes, int n_in,
                              void* d_out, int out_size) {
    const int* user          = (const int*)d_in[0];
    const int* question      = (const int*)d_in[1];
    const int* response      = (const int*)d_in[2];
    const int* mask          = (const int*)d_in[3];
    const int* q_neighbors   = (const int*)d_in[4];
    const int* s_neighbors   = (const int*)d_in[5];
    const int* u_neighbors   = (const int*)d_in[6];
    const int* q_neighbors_2 = (const int*)d_in[7];
    const int* qs_index      = (const int*)d_in[8];
    const float* emb_question   = (const float*)d_in[9];
    const float* emb_question_2 = (const float*)d_in[10];
    const float* emb_skill      = (const float*)d_in[11];
    const float* emb_user       = (const float*)d_in[12];
    const float* emb_response   = (const float*)d_in[13];
    const float* w1_q   = (const float*)d_in[14];
    const float* w2_q   = (const float*)d_in[15];
    const float* W_ih   = (const float*)d_in[16];
    const float* W_hh   = (const float*)d_in[17];
    const float* b_ih   = (const float*)d_in[18];
    const float* b_hh   = (const float*)d_in[19];
    const float* agg_w  = (const float*)d_in[20];
    const float* agg_b  = (const float*)d_in[21];
    const float* W_agg_last = (const float*)d_in[22];
    const float* b_agg_last = (const float*)d_in[23];
    const float* W_query = (const float*)d_in[24];
    const float* b_query = (const float*)d_in[25];
    const float* W_key   = (const float*)d_in[26];
    const float* b_key   = (const float*)d_in[27];
    const float* W_w     = (const float*)d_in[28];
    const float* b_w     = (const float*)d_in[29];
    const float* W_fusion = (const float*)d_in[30];
    const float* b_fusion = (const float*)d_in[31];
    float* out = (float*)d_out;

    prep_kernel<<<64, 256>>>(agg_w, W_agg_last, W_fusion, W_ih, W_hh,
                             W_query, b_query, W_key, b_key, W_w, b_w);
    phaseA_kernel<<<TS * BB, 128>>>(user, question, response, mask,
                                    q_neighbors, s_neighbors, u_neighbors, q_neighbors_2,
                                    qs_index, emb_question, emb_question_2, emb_skill,
                                    emb_user, emb_response, w1_q, w2_q,
                                    b_ih, b_hh, agg_b, b_agg_last, b_fusion);
    phaseB_kernel<<<BB, 256>>>(mask, out);
}

// round 9
// speedup vs baseline: 2.7797x; 2.7797x over previous
#include <cuda_runtime.h>
#include <math.h>
#include <float.h>
#include <limits.h>

#define BB 32
#define TT 50
#define DD 100
#define NBRN 6
#define SPQ 4
#define TS 49
#define RK 10
#define NINF (-INFINITY)
#define NU (TS * BB)

// ---------------- scratch (__device__ globals) ----------------
__device__ __align__(16) float g_WT_agg[3][DD * DD];   // [j][k*100+o]
__device__ __align__(16) float g_WT_last[DD * DD];     // [k*100+o]
__device__ __align__(16) float g_WT_fus[2 * DD * DD];  // [k*100+o]
__device__ __align__(16) float g_WT_ih[DD * 4 * DD];   // [k*400+o4]
__device__ __align__(16) float g_WhhT[DD * 4 * DD];    // [k*400+o4]
__device__ __align__(16) float g_qv[DD];
__device__ __align__(16) float g_kv[DD];
__device__ float g_scal[4];                            // qb, kb, bw
__device__ __align__(16) float g_eagg[2][NU][DD];
__device__ __align__(16) float g_xf[NU][2 * DD];
__device__ __align__(16) float g_et[NU][DD];
__device__ __align__(16) float g_pre[NU * 4 * DD];
__device__ __align__(16) float g_qs[NU * 5 * DD];
__device__ float g_ql[NU * 5];
__device__ int   g_idx[NU * RK];
__device__ int   g_sval[NU * 11];

// ---------------- prep ----------------
__global__ void prep_kernel(const float* __restrict__ agg_w,
                            const float* __restrict__ W_agg_last,
                            const float* __restrict__ W_fusion,
                            const float* __restrict__ W_ih,
                            const float* __restrict__ W_hh,
                            const float* __restrict__ W_query,
                            const float* __restrict__ b_query,
                            const float* __restrict__ W_key,
                            const float* __restrict__ b_key,
                            const float* __restrict__ W_w,
                            const float* __restrict__ b_w)
{
    int tid = blockIdx.x * blockDim.x + threadIdx.x;
    int nt = gridDim.x * blockDim.x;
    for (int i = tid; i < 3 * DD * DD; i += nt) {
        int j = i / (DD * DD), rem = i % (DD * DD);
        int o = rem / DD, k = rem % DD;
        g_WT_agg[j][k * DD + o] = agg_w[i];
    }
    for (int i = tid; i < DD * DD; i += nt) {
        int o = i / DD, k = i % DD;
        g_WT_last[k * DD + o] = W_agg_last[i];
    }
    for (int i = tid; i < DD * 2 * DD; i += nt) {
        int o = i / (2 * DD), k = i % (2 * DD);
        g_WT_fus[k * DD + o] = W_fusion[i];
    }
    for (int i = tid; i < 4 * DD * DD; i += nt) {
        int o4 = i / DD, k = i % DD;
        g_WT_ih[k * 4 * DD + o4] = W_ih[i];
    }
    for (int i = tid; i < 4 * DD * DD; i += nt) {
        int o4 = i / DD, k = i % DD;
        g_WhhT[k * 4 * DD + o4] = W_hh[i];
    }
    for (int k = tid; k < DD; k += nt) {
        float a = 0.f, bs = 0.f;
        for (int o = 0; o < DD; o++) {
            a  += W_query[o * DD + k] * W_w[o];
            bs += W_key[o * DD + k] * W_w[DD + o];
        }
        g_qv[k] = a;
        g_kv[k] = bs;
    }
    if (tid == 0) {
        float qb = 0.f, kb = 0.f;
        for (int o = 0; o < DD; o++) {
            qb += b_query[o] * W_w[o];
            kb += b_key[o] * W_w[DD + o];
        }
        g_scal[0] = qb; g_scal[1] = kb; g_scal[2] = b_w[0];
    }
}

// tiled matvec with weight double-buffer prefetch:
// sOut[r*DD+tid] = act(bias[tid] + sum_k sIn[r*KK+k]*WT[k*DD+tid])
// ACT: 0 = tanh, 1 = relu
template <int TR, int KK, int ACT>
__device__ __forceinline__ void mv_tile(const float* __restrict__ WT,
                                        const float* __restrict__ bias,
                                        const float* __restrict__ sIn,
                                        float* __restrict__ sOut, int tid)
{
    if (tid < DD) {
        float acc[TR];
#pragma unroll
        for (int r = 0; r < TR; r++) acc[r] = 0.f;
        float c0 = WT[0 * DD + tid], c1 = WT[1 * DD + tid];
        float c2 = WT[2 * DD + tid], c3 = WT[3 * DD + tid];
#pragma unroll 1
        for (int k = 0; k < KK; k += 4) {
            float n0 = 0.f, n1 = 0.f, n2 = 0.f, n3 = 0.f;
            if (k + 4 < KK) {
                n0 = WT[(k + 4) * DD + tid];
                n1 = WT[(k + 5) * DD + tid];
                n2 = WT[(k + 6) * DD + tid];
                n3 = WT[(k + 7) * DD + tid];
            }
#pragma unroll
            for (int r = 0; r < TR; r++) {
                const float4 s4 = *reinterpret_cast<const float4*>(sIn + r * KK + k);
                acc[r] = fmaf(s4.x, c0, acc[r]);
                acc[r] = fmaf(s4.y, c1, acc[r]);
                acc[r] = fmaf(s4.z, c2, acc[r]);
                acc[r] = fmaf(s4.w, c3, acc[r]);
            }
            c0 = n0; c1 = n1; c2 = n2; c3 = n3;
        }
        float bv = bias[tid];
#pragma unroll
        for (int r = 0; r < TR; r++) {
            float v = acc[r] + bv;
            sOut[r * DD + tid] = (ACT == 0) ? tanhf(v) : fmaxf(v, 0.f);
        }
    }
}

// ---------------- agg: one (side, t, b) per block ----------------
__global__ __launch_bounds__(128) void agg_kernel(
    const int* __restrict__ user, const int* __restrict__ question,
    const int* __restrict__ mask,
    const int* __restrict__ q_neighbors, const int* __restrict__ s_neighbors,
    const int* __restrict__ u_neighbors, const int* __restrict__ q_neighbors_2,
    const float* __restrict__ emb_question, const float* __restrict__ emb_question_2,
    const float* __restrict__ emb_skill, const float* __restrict__ emb_user,
    const float* __restrict__ agg_b, const float* __restrict__ b_agg_last)
{
    __shared__ int l1[NBRN];
    __shared__ int l2[36];
    __shared__ int l3[216];
    __shared__ __align__(16) float s2[36 * DD];
    __shared__ __align__(16) float e2[36 * DD];
    __shared__ __align__(16) float s1[6 * DD];
    __shared__ __align__(16) float e1[6 * DD];
    __shared__ __align__(16) float s0[DD];
    __shared__ __align__(16) float e0v[DD];

    const int unit = blockIdx.x;
    const int side = blockIdx.y;
    const int t = unit / BB;
    const int b = unit % BB;
    const int tid = threadIdx.x;
    const float inv6 = 1.0f / 6.0f;

    if (!mask[b * TT + t]) return;

    int node;
    const int *tabA, *tabB;
    const float *embX, *embY;
    if (side == 0) {
        node = question[b * TT + t];
        tabA = q_neighbors; tabB = s_neighbors;
        embX = emb_question; embY = emb_skill;
    } else {
        node = user[b * TT + t];
        tabA = u_neighbors; tabB = q_neighbors_2;
        embX = emb_user; embY = emb_question_2;
    }
    if (tid < NBRN) l1[tid] = tabA[node * NBRN + tid];
    __syncthreads();
    if (tid < 36) l2[tid] = tabB[l1[tid / 6] * NBRN + tid % 6];
    __syncthreads();
    for (int i = tid; i < 216; i += blockDim.x)
        l3[i] = tabA[l2[i / 6] * NBRN + i % 6];
    __syncthreads();

    // build s-vectors (pre-sweep inputs)
    for (int idx = tid; idx < 3600; idx += blockDim.x) {
        const int p = idx / DD, k = idx - p * DD;
        float mm = 0.f;
#pragma unroll
        for (int l = 0; l < 6; l++) mm += embY[(size_t)l3[p * 6 + l] * DD + k];
        s2[p * DD + k] = embX[(size_t)l2[p] * DD + k] + mm * inv6;
    }
    if (tid < DD) {
        const int k = tid;
        float mm = 0.f;
#pragma unroll
        for (int i = 0; i < 6; i++) mm += embY[(size_t)l1[i] * DD + k];
        s0[k] = embX[(size_t)node * DD + k] + mm * inv6;
        for (int i = 0; i < 6; i++) {
            float m2 = 0.f;
#pragma unroll
            for (int j = 0; j < 6; j++) m2 += embX[(size_t)l2[i * 6 + j] * DD + k];
            s1[i * DD + k] = embY[(size_t)l1[i] * DD + k] + m2 * inv6;
        }
    }
    __syncthreads();
    // sweep i=0
    mv_tile<36, DD, 0>(g_WT_agg[2], agg_b + 2 * DD, s2, e2, tid);
    mv_tile<6, DD, 0>(g_WT_agg[1], agg_b + 1 * DD, s1, e1, tid);
    mv_tile<1, DD, 0>(g_WT_agg[0], agg_b + 0 * DD, s0, e0v, tid);
    __syncthreads();
    // sweep i=1 (build from pre-update values)
    if (tid < DD) {
        const int k = tid;
        float nm[6];
        for (int i = 0; i < 6; i++) {
            float mm = 0.f;
#pragma unroll
            for (int j = 0; j < 6; j++) mm += e2[(i * 6 + j) * DD + k];
            nm[i] = e1[i * DD + k] + mm * inv6;
        }
        float mm = 0.f;
#pragma unroll
        for (int i = 0; i < 6; i++) mm += e1[i * DD + k];
        s0[k] = e0v[k] + mm * inv6;
        for (int i = 0; i < 6; i++) s1[i * DD + k] = nm[i];
    }
    __syncthreads();
    mv_tile<6, DD, 0>(g_WT_agg[1], agg_b + 1 * DD, s1, e1, tid);
    mv_tile<1, DD, 0>(g_WT_agg[0], agg_b + 0 * DD, s0, e0v, tid);
    __syncthreads();
    // sweep i=2
    if (tid < DD) {
        const int k = tid;
        float mm = 0.f;
#pragma unroll
        for (int i = 0; i < 6; i++) mm += e1[i * DD + k];
        s0[k] = e0v[k] + mm * inv6;
    }
    __syncthreads();
    mv_tile<1, DD, 0>(g_WT_agg[0], agg_b + 0 * DD, s0, e0v, tid);
    __syncthreads();
    mv_tile<1, DD, 0>(g_WT_last, b_agg_last, e0v, s0, tid);
    if (tid < DD) g_eagg[side][unit][tid] = s0[tid];
}

// ---------------- mid: ehat/xf + attention precompute + top-k ----------------
__global__ __launch_bounds__(128) void mid_kernel(
    const int* __restrict__ question, const int* __restrict__ response,
    const int* __restrict__ mask, const int* __restrict__ qs_index,
    const float* __restrict__ emb_question, const float* __restrict__ emb_question_2,
    const float* __restrict__ emb_skill, const float* __restrict__ emb_response,
    const float* __restrict__ w1_q, const float* __restrict__ w2_q)
{
    __shared__ __align__(16) float qs_s[5 * DD];
    __shared__ float scores[TT];

    const int unit = blockIdx.x;
    const int t = unit / BB;
    const int b = unit % BB;
    const int tid = threadIdx.x;

    const int q_t = question[b * TT + t];
    const int r_t = response[b * TT + t];
    const int m = mask[b * TT + t];
    const float w1 = w1_q[0], w2 = w2_q[0];

    if (tid < DD) {
        float eh;
        if (m) eh = w1 * g_eagg[0][unit][tid] + w2 * g_eagg[1][unit][tid];
        else   eh = w1 * emb_question[(size_t)q_t * DD + tid]
                  + w2 * emb_question_2[(size_t)q_t * DD + tid];
        g_xf[unit][tid] = eh;
        g_xf[unit][DD + tid] = emb_response[r_t * DD + tid];
    }

    // attention precompute
    const int qn = question[b * TT + t + 1];
    if (tid < DD) {
        const int k = tid;
        float v = emb_question[(size_t)qn * DD + k];
        qs_s[k] = v;
        g_qs[(size_t)unit * 5 * DD + k] = v;
#pragma unroll
        for (int j = 0; j < 4; j++) {
            int sidx = qs_index[qn * SPQ + j];
            v = emb_skill[(size_t)sidx * DD + k];
            qs_s[(1 + j) * DD + k] = v;
            g_qs[(size_t)unit * 5 * DD + (1 + j) * DD + k] = v;
        }
    }
    __syncthreads();
    if (tid < 5) {
        float acc = g_scal[0];
        for (int k = 0; k < DD; k++) acc += qs_s[tid * DD + k] * g_qv[k];
        g_ql[unit * 5 + tid] = acc;
    }
    if (tid < TT) {
        const int tp = tid;
        float sc = NINF;
        if (tp < t) {
            const int qq = question[b * TT + tp];
            float acc = 0.f;
            for (int k = 0; k < DD; k++) acc += emb_question[(size_t)qq * DD + k] * qs_s[k];
            sc = acc;
        }
        scores[tp] = sc;
    }
    __syncthreads();
    // top-10 (warp 0), lax.top_k semantics: values desc, lower index first on ties.
    if (tid < 32) {
        float v0 = (tid < TT) ? scores[tid] : NINF;
        float v1 = (tid + 32 < TT) ? scores[tid + 32] : NINF;
        int idx0 = (tid < TT) ? tid : INT_MAX;
        int idx1 = (tid + 32 < TT) ? (tid + 32) : INT_MAX;
        for (int r = 0; r < RK; r++) {
            float bv; int bi;
            if (v1 > v0 || (v1 == v0 && idx1 < idx0)) { bv = v1; bi = idx1; }
            else { bv = v0; bi = idx0; }
#pragma unroll
            for (int off = 16; off; off >>= 1) {
                float ov = __shfl_xor_sync(0xffffffffu, bv, off);
                int oi = __shfl_xor_sync(0xffffffffu, bi, off);
                if (ov > bv || (ov == bv && oi < bi)) { bv = ov; bi = oi; }
            }
            if (tid == 0) {
                g_idx[unit * RK + r] = bi;
                g_sval[unit * 11 + 1 + r] = (bi < t) ? 1 : 0;
            }
            if (idx0 == bi) { v0 = NINF; idx0 = INT_MAX; }
            if (idx1 == bi) { v1 = NINF; idx1 = INT_MAX; }
        }
        if (tid == 0) g_sval[unit * 11 + 0] = 1;
    }
}

// ---------------- fus_gemm: g_et = relu(g_xf @ W_fus^T + b), 32 rows/block --
__global__ __launch_bounds__(128) void fus_gemm(const float* __restrict__ b_fusion)
{
    __shared__ __align__(16) float xs[32 * 2 * DD];
    const int r0 = blockIdx.x * 32;
    const int tid = threadIdx.x;
    const float4* src = reinterpret_cast<const float4*>(&g_xf[r0][0]);
    float4* dst = reinterpret_cast<float4*>(xs);
    for (int i = tid; i < 32 * 2 * DD / 4; i += blockDim.x) dst[i] = src[i];
    __syncthreads();
    mv_tile<32, 2 * DD, 1>(g_WT_fus, b_fusion, xs, &g_et[r0][0], tid);
}

// ---------------- pre_gemm: g_pre = g_et @ W_ih^T + b_ih + b_hh ------------
__global__ __launch_bounds__(512) void pre_gemm(const float* __restrict__ b_ih,
                                                const float* __restrict__ b_hh)
{
    __shared__ __align__(16) float es[32 * DD];
    const int r0 = blockIdx.x * 32;
    const int tid = threadIdx.x;
    const float4* src = reinterpret_cast<const float4*>(&g_et[r0][0]);
    float4* dst = reinterpret_cast<float4*>(es);
    for (int i = tid; i < 32 * DD / 4; i += blockDim.x) dst[i] = src[i];
    __syncthreads();
    if (tid < 4 * DD) {
        float acc[32];
#pragma unroll
        for (int r = 0; r < 32; r++) acc[r] = 0.f;
#pragma unroll 1
        for (int k = 0; k < DD; k += 4) {
            const float w0 = g_WT_ih[(k + 0) * 4 * DD + tid];
            const float w1 = g_WT_ih[(k + 1) * 4 * DD + tid];
            const float w2 = g_WT_ih[(k + 2) * 4 * DD + tid];
            const float w3 = g_WT_ih[(k + 3) * 4 * DD + tid];
#pragma unroll
            for (int r = 0; r < 32; r++) {
                const float4 e4 = *reinterpret_cast<const float4*>(es + r * DD + k);
                acc[r] = fmaf(e4.x, w0, acc[r]);
                acc[r] = fmaf(e4.y, w1, acc[r]);
                acc[r] = fmaf(e4.z, w2, acc[r]);
                acc[r] = fmaf(e4.w, w3, acc[r]);
            }
        }
        const float bias = b_ih[tid] + b_hh[tid];
#pragma unroll
        for (int r = 0; r < 32; r++)
            g_pre[(size_t)(r0 + r) * 4 * DD + tid] = acc[r] + bias;
    }
}

// ---------------- Phase B: per-batch-row LSTM + attention ----------------
// 800 threads: tid<800 are gate threads (half = tid/400, o4 = tid%400),
// each holds a 48/52-element k-slice of W_hh column o4 in registers.
__global__ __launch_bounds__(800) void phaseB_kernel(const int* __restrict__ mask,
                                                     float* __restrict__ out)
{
    __shared__ __align__(16) float h[DD];
    __shared__ __align__(16) float cst[DD];
    __shared__ __align__(16) float sh[TT * DD];
    __shared__ __align__(16) float qs_sm[2][5 * DD];
    __shared__ __align__(16) float kv_s[DD];
    __shared__ float part[800];
    __shared__ float dots[2][66];
    __shared__ int idx_s[2][RK];
    __shared__ int sval_s[2][11];
    __shared__ float ql_s[2][5];

    const int b = blockIdx.x;
    const int tid = threadIdx.x;
    const int half = tid / 400;          // 0 or 1
    const int o4 = tid - half * 400;     // 0..399
    const int kbase = half ? 48 : 0;

    // register-resident W_hh slice (load 52 unconditionally; half 0 uses 48)
    float wreg[52];
#pragma unroll
    for (int kk = 0; kk < 52; kk++)
        wreg[kk] = g_WhhT[(kbase + kk) * 4 * DD + o4];

    for (int i = tid; i < TT * DD; i += blockDim.x) sh[i] = 0.f;
    if (tid < DD) { h[tid] = 0.f; cst[tid] = 0.f; kv_s[tid] = g_kv[tid]; }
    if (tid == 0) out[b * TT + 0] = 0.5f;
    __syncthreads();

    for (int t = 0; t < TS; t++) {
        const int row = t * BB + b;
        const int par = t & 1;

        // prefetch step data (ping-pong buffers; readers are after barrier 2)
        if (tid < 500) qs_sm[par][tid] = g_qs[(size_t)row * 5 * DD + tid];
        else if (tid < 510) idx_s[par][tid - 500] = g_idx[row * RK + (tid - 500)];
        else if (tid < 521) sval_s[par][tid - 510] = g_sval[row * 11 + (tid - 510)];
        else if (tid < 526) ql_s[par][tid - 521] = g_ql[row * 5 + (tid - 521)];

        // gates: partial dot over this thread's k-slice
        {
            float a = half ? 0.f : g_pre[(size_t)row * 4 * DD + o4];
            if (half == 0) {
#pragma unroll
                for (int g4 = 0; g4 < 12; g4++) {
                    const float4 h4 = *reinterpret_cast<const float4*>(h + 4 * g4);
                    a = fmaf(h4.x, wreg[4 * g4 + 0], a);
                    a = fmaf(h4.y, wreg[4 * g4 + 1], a);
                    a = fmaf(h4.z, wreg[4 * g4 + 2], a);
                    a = fmaf(h4.w, wreg[4 * g4 + 3], a);
                }
            } else {
#pragma unroll
                for (int g4 = 0; g4 < 13; g4++) {
                    const float4 h4 = *reinterpret_cast<const float4*>(h + 48 + 4 * g4);
                    a = fmaf(h4.x, wreg[4 * g4 + 0], a);
                    a = fmaf(h4.y, wreg[4 * g4 + 1], a);
                    a = fmaf(h4.z, wreg[4 * g4 + 2], a);
                    a = fmaf(h4.w, wreg[4 * g4 + 3], a);
                }
            }
            part[tid] = a;
        }
        __syncthreads();   // b1: gates done

        // combine gates, LSTM cell update (threads 0..99)
        if (tid < DD) {
            const int o = tid;
            const float ai = part[o]            + part[400 + o];
            const float af = part[DD + o]       + part[400 + DD + o];
            const float ag = part[2 * DD + o]   + part[400 + 2 * DD + o];
            const float ao = part[3 * DD + o]   + part[400 + 3 * DD + o];
            const int m = mask[b * TT + t];
            const float ig = 1.f / (1.f + expf(-ai));
            const float fg = 1.f / (1.f + expf(-af));
            const float gg = tanhf(ag);
            const float og = 1.f / (1.f + expf(-ao));
            const float c2 = fg * cst[o] + ig * gg;
            const float h2 = og * tanhf(c2);
            const float hn = m ? h2 : h[o];
            const float cn = m ? c2 : cst[o];
            h[o] = hn; cst[o] = cn; sh[t * DD + o] = hn;
        }
        __syncthreads();   // b2: h/sh updated

        // 66 dots: d<55 -> qs[q]·states[s]; d>=55 -> states[s]·kv
        {
            const int wid = tid >> 5, lane = tid & 31;
            for (int d = wid; d < 66; d += 25) {
                const float* av;
                const float* bv;
                if (d < 55) {
                    const int q = d / 11, s = d % 11;
                    av = &qs_sm[par][q * DD];
                    bv = (s == 0) ? h : &sh[idx_s[par][s - 1] * DD];
                } else {
                    const int s = d - 55;
                    av = kv_s;
                    bv = (s == 0) ? h : &sh[idx_s[par][s - 1] * DD];
                }
                float acc = av[lane] * bv[lane] + av[lane + 32] * bv[lane + 32]
                          + av[lane + 64] * bv[lane + 64];
                if (lane < 4) acc += av[lane + 96] * bv[lane + 96];
#pragma unroll
                for (int off = 16; off; off >>= 1)
                    acc += __shfl_xor_sync(0xffffffffu, acc, off);
                if (lane == 0) dots[par][d] = acc;
            }
        }
        __syncthreads();   // b3: dots done; warp0 softmax overlaps next step

        if (tid < 32) {
            const float kbbw = g_scal[1] + g_scal[2];
            const int j0 = tid, j1 = tid + 32;
            float l0 = NINF, l1v = NINF, g0 = 0.f, g1 = 0.f;
            if (j0 < 55) {
                const int q = j0 / 11, s = j0 % 11;
                if (sval_s[par][s]) l0 = ql_s[par][q] + dots[par][55 + s] + kbbw;
                g0 = dots[par][j0];
            }
            if (j1 < 55) {
                const int q = j1 / 11, s = j1 % 11;
                if (sval_s[par][s]) l1v = ql_s[par][q] + dots[par][55 + s] + kbbw;
                g1 = dots[par][j1];
            }
            float mx = fmaxf(l0, l1v);
#pragma unroll
            for (int off = 16; off; off >>= 1)
                mx = fmaxf(mx, __shfl_xor_sync(0xffffffffu, mx, off));
            float e0 = (l0 == NINF) ? 0.f : expf(l0 - mx);
            float e1 = (l1v == NINF) ? 0.f : expf(l1v - mx);
            float es = e0 + e1;
            float ws = e0 * g0 + e1 * g1;
#pragma unroll
            for (int off = 16; off; off >>= 1) {
                es += __shfl_xor_sync(0xffffffffu, es, off);
                ws += __shfl_xor_sync(0xffffffffu, ws, off);
            }
            if (tid == 0)
                out[b * TT + t + 1] = 1.f / (1.f + expf(-(ws / es)));
        }
        // no trailing barrier: next step writes opposite-parity buffers; `part`
        // is rewritten only after b3; h changes only after next b1.
    }
}

extern "C" void kernel_launch(void* const* d_in, const int* in_sizes, int n_in,
                              void* d_out, int out_size) {
    const int* user          = (const int*)d_in[0];
    const int* question      = (const int*)d_in[1];
    const int* response      = (const int*)d_in[2];
    const int* mask          = (const int*)d_in[3];
    const int* q_neighbors   = (const int*)d_in[4];
    const int* s_neighbors   = (const int*)d_in[5];
    const int* u_neighbors   = (const int*)d_in[6];
    const int* q_neighbors_2 = (const int*)d_in[7];
    const int* qs_index      = (const int*)d_in[8];
    const float* emb_question   = (const float*)d_in[9];
    const float* emb_question_2 = (const float*)d_in[10];
    const float* emb_skill      = (const float*)d_in[11];
    const float* emb_user       = (const float*)d_in[12];
    const float* emb_response   = (const float*)d_in[13];
    const float* w1_q   = (const float*)d_in[14];
    const float* w2_q   = (const float*)d_in[15];
    const float* W_ih   = (const float*)d_in[16];
    const float* W_hh   = (const float*)d_in[17];
    const float* b_ih   = (const float*)d_in[18];
    const float* b_hh   = (const float*)d_in[19];
    const float* agg_w  = (const float*)d_in[20];
    const float* agg_b  = (const float*)d_in[21];
    const float* W_agg_last = (const float*)d_in[22];
    const float* b_agg_last = (const float*)d_in[23];
    const float* W_query = (const float*)d_in[24];
    const float* b_query = (const float*)d_in[25];
    const float* W_key   = (const float*)d_in[26];
    const float* b_key   = (const float*)d_in[27];
    const float* W_w     = (const float*)d_in[28];
    const float* b_w     = (const float*)d_in[29];
    const float* W_fusion = (const float*)d_in[30];
    const float* b_fusion = (const float*)d_in[31];
    float* out = (float*)d_out;

    prep_kernel<<<132, 256>>>(agg_w, W_agg_last, W_fusion, W_ih, W_hh,
                              W_query, b_query, W_key, b_key, W_w, b_w);
    dim3 agrid(NU, 2);
    agg_kernel<<<agrid, 128>>>(user, question, mask,
                               q_neighbors, s_neighbors, u_neighbors, q_neighbors_2,
                               emb_question, emb_question_2, emb_skill, emb_user,
                               agg_b, b_agg_last);
    mid_kernel<<<NU, 128>>>(question, response, mask, qs_index,
                            emb_question, emb_question_2, emb_skill, emb_response,
                            w1_q, w2_q);
    fus_gemm<<<NU / 32, 128>>>(b_fusion);
    pre_gemm<<<NU / 32, 512>>>(b_ih, b_hh);
    phaseB_kernel<<<BB, 800>>>(mask, out);
}

// round 11
// speedup vs baseline: 3.2290x; 1.1616x over previous
#include <cuda_runtime.h>
#include <math.h>
#include <float.h>
#include <limits.h>

#define BB 32
#define TT 50
#define DD 100
#define NBRN 6
#define SPQ 4
#define TS 49
#define RK 10
#define NINF (-INFINITY)
#define NU (TS * BB)

// ---------------- scratch (__device__ globals) ----------------
__device__ __align__(16) float g_WT_agg[3][DD * DD];   // [j][k*100+o]
__device__ __align__(16) float g_WT_last[DD * DD];     // [k*100+o]
__device__ __align__(16) float g_WT_fus[2 * DD * DD];  // [k*100+o]
__device__ __align__(16) float g_WT_ih[DD * 4 * DD];   // [k*400+o4]
__device__ __align__(16) float g_WhhT[DD * 4 * DD];    // [k*400+o4]
__device__ __align__(16) float g_qv[DD];
__device__ __align__(16) float g_kv[DD];
__device__ float g_scal[4];                            // qb, kb, bw
__device__ __align__(16) float g_eagg[2][NU][DD];
__device__ __align__(16) float g_xf[NU][2 * DD];
__device__ __align__(16) float g_et[NU][DD];
__device__ __align__(16) float g_pre[NU * 4 * DD];
__device__ __align__(16) float g_qs[NU * 5 * DD];
__device__ float g_ql[NU * 5];
__device__ int   g_idx[NU * RK];
__device__ int   g_sval[NU * 11];

// ---------------- prep ----------------
__global__ void prep_kernel(const float* __restrict__ agg_w,
                            const float* __restrict__ W_agg_last,
                            const float* __restrict__ W_fusion,
                            const float* __restrict__ W_ih,
                            const float* __restrict__ W_hh,
                            const float* __restrict__ W_query,
                            const float* __restrict__ b_query,
                            const float* __restrict__ W_key,
                            const float* __restrict__ b_key,
                            const float* __restrict__ W_w,
                            const float* __restrict__ b_w)
{
    int tid = blockIdx.x * blockDim.x + threadIdx.x;
    int nt = gridDim.x * blockDim.x;
    for (int i = tid; i < 3 * DD * DD; i += nt) {
        int j = i / (DD * DD), rem = i % (DD * DD);
        int o = rem / DD, k = rem % DD;
        g_WT_agg[j][k * DD + o] = agg_w[i];
    }
    for (int i = tid; i < DD * DD; i += nt) {
        int o = i / DD, k = i % DD;
        g_WT_last[k * DD + o] = W_agg_last[i];
    }
    for (int i = tid; i < DD * 2 * DD; i += nt) {
        int o = i / (2 * DD), k = i % (2 * DD);
        g_WT_fus[k * DD + o] = W_fusion[i];
    }
    for (int i = tid; i < 4 * DD * DD; i += nt) {
        int o4 = i / DD, k = i % DD;
        g_WT_ih[k * 4 * DD + o4] = W_ih[i];
    }
    for (int i = tid; i < 4 * DD * DD; i += nt) {
        int o4 = i / DD, k = i % DD;
        g_WhhT[k * 4 * DD + o4] = W_hh[i];
    }
    for (int k = tid; k < DD; k += nt) {
        float a = 0.f, bs = 0.f;
        for (int o = 0; o < DD; o++) {
            a  += W_query[o * DD + k] * W_w[o];
            bs += W_key[o * DD + k] * W_w[DD + o];
        }
        g_qv[k] = a;
        g_kv[k] = bs;
    }
    if (tid == 0) {
        float qb = 0.f, kb = 0.f;
        for (int o = 0; o < DD; o++) {
            qb += b_query[o] * W_w[o];
            kb += b_key[o] * W_w[DD + o];
        }
        g_scal[0] = qb; g_scal[1] = kb; g_scal[2] = b_w[0];
    }
}

// tiled matvec with weight double-buffer prefetch:
// sOut[r*DD+tid] = act(bias[tid] + sum_k sIn[r*KK+k]*WT[k*DD+tid])
// ACT: 0 = tanh, 1 = relu. Active only for 0 <= tid < DD.
template <int TR, int KK, int ACT>
__device__ __forceinline__ void mv_tile(const float* __restrict__ WT,
                                        const float* __restrict__ bias,
                                        const float* __restrict__ sIn,
                                        float* __restrict__ sOut, int tid)
{
    if (tid >= 0 && tid < DD) {
        float acc[TR];
#pragma unroll
        for (int r = 0; r < TR; r++) acc[r] = 0.f;
        float c0 = WT[0 * DD + tid], c1 = WT[1 * DD + tid];
        float c2 = WT[2 * DD + tid], c3 = WT[3 * DD + tid];
#pragma unroll 1
        for (int k = 0; k < KK; k += 4) {
            float n0 = 0.f, n1 = 0.f, n2 = 0.f, n3 = 0.f;
            if (k + 4 < KK) {
                n0 = WT[(k + 4) * DD + tid];
                n1 = WT[(k + 5) * DD + tid];
                n2 = WT[(k + 6) * DD + tid];
                n3 = WT[(k + 7) * DD + tid];
            }
#pragma unroll
            for (int r = 0; r < TR; r++) {
                const float4 s4 = *reinterpret_cast<const float4*>(sIn + r * KK + k);
                acc[r] = fmaf(s4.x, c0, acc[r]);
                acc[r] = fmaf(s4.y, c1, acc[r]);
                acc[r] = fmaf(s4.z, c2, acc[r]);
                acc[r] = fmaf(s4.w, c3, acc[r]);
            }
            c0 = n0; c1 = n1; c2 = n2; c3 = n3;
        }
        float bv = bias[tid];
#pragma unroll
        for (int r = 0; r < TR; r++) {
            float v = acc[r] + bv;
            sOut[r * DD + tid] = (ACT == 0) ? tanhf(v) : fmaxf(v, 0.f);
        }
    }
}

// ---------------- agg: one (side, t, b) per block, 256 threads ----------------
// Lower half (tid 0..127, lane lt=tid) and upper half (tid 128..255, lane
// ut=tid-128) run different matvecs concurrently; barriers only at data joins.
__global__ __launch_bounds__(256) void agg_kernel(
    const int* __restrict__ user, const int* __restrict__ question,
    const int* __restrict__ mask,
    const int* __restrict__ q_neighbors, const int* __restrict__ s_neighbors,
    const int* __restrict__ u_neighbors, const int* __restrict__ q_neighbors_2,
    const float* __restrict__ emb_question, const float* __restrict__ emb_question_2,
    const float* __restrict__ emb_skill, const float* __restrict__ emb_user,
    const float* __restrict__ agg_b, const float* __restrict__ b_agg_last)
{
    __shared__ int l1[NBRN];
    __shared__ int l2[36];
    __shared__ int l3[216];
    __shared__ __align__(16) float s2[36 * DD];
    __shared__ __align__(16) float e2[36 * DD];
    __shared__ __align__(16) float s1[6 * DD];
    __shared__ __align__(16) float e1[6 * DD];
    __shared__ __align__(16) float s0[DD];
    __shared__ __align__(16) float e0v[DD];

    const int unit = blockIdx.x;
    const int side = blockIdx.y;
    const int t = unit / BB;
    const int b = unit % BB;
    const int tid = threadIdx.x;
    const int lt = tid;           // lower lane (valid < DD)
    const int ut = tid - 128;     // upper lane (valid 0..DD-1)
    const float inv6 = 1.0f / 6.0f;

    if (!mask[b * TT + t]) return;

    int node;
    const int *tabA, *tabB;
    const float *embX, *embY;
    if (side == 0) {
        node = question[b * TT + t];
        tabA = q_neighbors; tabB = s_neighbors;
        embX = emb_question; embY = emb_skill;
    } else {
        node = user[b * TT + t];
        tabA = u_neighbors; tabB = q_neighbors_2;
        embX = emb_user; embY = emb_question_2;
    }
    if (tid < NBRN) l1[tid] = tabA[node * NBRN + tid];
    __syncthreads();
    if (tid < 36) l2[tid] = tabB[l1[tid / 6] * NBRN + tid % 6];
    __syncthreads();
    if (tid < 216) l3[tid] = tabA[l2[tid / 6] * NBRN + tid % 6];
    __syncthreads();

    // build s-vectors (pre-sweep inputs); s2 flat over all 256 threads
    for (int idx = tid; idx < 3600; idx += 256) {
        const int p = idx / DD, k = idx - p * DD;
        float mm = 0.f;
#pragma unroll
        for (int l = 0; l < 6; l++) mm += embY[(size_t)l3[p * 6 + l] * DD + k];
        s2[p * DD + k] = embX[(size_t)l2[p] * DD + k] + mm * inv6;
    }
    if (tid < DD) {
        const int k = lt;
        float mm = 0.f;
#pragma unroll
        for (int i = 0; i < 6; i++) mm += embY[(size_t)l1[i] * DD + k];
        s0[k] = embX[(size_t)node * DD + k] + mm * inv6;
        for (int i = 0; i < 3; i++) {
            float m2 = 0.f;
#pragma unroll
            for (int j = 0; j < 6; j++) m2 += embX[(size_t)l2[i * 6 + j] * DD + k];
            s1[i * DD + k] = embY[(size_t)l1[i] * DD + k] + m2 * inv6;
        }
    } else if (ut >= 0 && ut < DD) {
        const int k = ut;
        for (int i = 3; i < 6; i++) {
            float m2 = 0.f;
#pragma unroll
            for (int j = 0; j < 6; j++) m2 += embX[(size_t)l2[i * 6 + j] * DD + k];
            s1[i * DD + k] = embY[(size_t)l1[i] * DD + k] + m2 * inv6;
        }
    }
    __syncthreads();

    // sweep i=0: halves run G2a+G1 | G2b+G0 concurrently
    if (tid < 128) {
        mv_tile<18, DD, 0>(g_WT_agg[2], agg_b + 2 * DD, s2, e2, lt);
        mv_tile<6, DD, 0>(g_WT_agg[1], agg_b + 1 * DD, s1, e1, lt);
    } else {
        mv_tile<18, DD, 0>(g_WT_agg[2], agg_b + 2 * DD, s2 + 18 * DD, e2 + 18 * DD, ut);
        mv_tile<1, DD, 0>(g_WT_agg[0], agg_b + 0 * DD, s0, e0v, ut);
    }
    __syncthreads();

    // combine for sweep i=1 (from pre-update values)
    if (tid < DD) {
        const int k = lt;
        float nm[6];
        for (int i = 0; i < 6; i++) {
            float mm = 0.f;
#pragma unroll
            for (int j = 0; j < 6; j++) mm += e2[(i * 6 + j) * DD + k];
            nm[i] = e1[i * DD + k] + mm * inv6;
        }
        for (int i = 0; i < 6; i++) s1[i * DD + k] = nm[i];
    } else if (ut >= 0 && ut < DD) {
        const int k = ut;
        float mm = 0.f;
#pragma unroll
        for (int i = 0; i < 6; i++) mm += e1[i * DD + k];
        s0[k] = e0v[k] + mm * inv6;
    }
    __syncthreads();

    // sweep i=1: G1 | G0 concurrently
    if (tid < 128) {
        mv_tile<6, DD, 0>(g_WT_agg[1], agg_b + 1 * DD, s1, e1, lt);
    } else {
        mv_tile<1, DD, 0>(g_WT_agg[0], agg_b + 0 * DD, s0, e0v, ut);
    }
    __syncthreads();

    // combine for sweep i=2
    if (tid < DD) {
        const int k = lt;
        float mm = 0.f;
#pragma unroll
        for (int i = 0; i < 6; i++) mm += e1[i * DD + k];
        s0[k] = e0v[k] + mm * inv6;
    }
    __syncthreads();
    // sweep i=2 + final layer (lower half; serial dependency)
    mv_tile<1, DD, 0>(g_WT_agg[0], agg_b + 0 * DD, s0, e0v, lt);
    __syncthreads();
    mv_tile<1, DD, 0>(g_WT_last, b_agg_last, e0v, s0, lt);
    if (tid < DD) g_eagg[side][unit][tid] = s0[tid];
}

// ---------------- mid: ehat/xf + attention precompute + top-k ----------------
__global__ __launch_bounds__(128) void mid_kernel(
    const int* __restrict__ question, const int* __restrict__ response,
    const int* __restrict__ mask, const int* __restrict__ qs_index,
    const float* __restrict__ emb_question, const float* __restrict__ emb_question_2,
    const float* __restrict__ emb_skill, const float* __restrict__ emb_response,
    const float* __restrict__ w1_q, const float* __restrict__ w2_q)
{
    __shared__ __align__(16) float qs_s[5 * DD];
    __shared__ float scores[TT];

    const int unit = blockIdx.x;
    const int t = unit / BB;
    const int b = unit % BB;
    const int tid = threadIdx.x;

    const int q_t = question[b * TT + t];
    const int r_t = response[b * TT + t];
    const int m = mask[b * TT + t];
    const float w1 = w1_q[0], w2 = w2_q[0];

    if (tid < DD) {
        float eh;
        if (m) eh = w1 * g_eagg[0][unit][tid] + w2 * g_eagg[1][unit][tid];
        else   eh = w1 * emb_question[(size_t)q_t * DD + tid]
                  + w2 * emb_question_2[(size_t)q_t * DD + tid];
        g_xf[unit][tid] = eh;
        g_xf[unit][DD + tid] = emb_response[r_t * DD + tid];
    }

    // attention precompute
    const int qn = question[b * TT + t + 1];
    if (tid < DD) {
        const int k = tid;
        float v = emb_question[(size_t)qn * DD + k];
        qs_s[k] = v;
        g_qs[(size_t)unit * 5 * DD + k] = v;
#pragma unroll
        for (int j = 0; j < 4; j++) {
            int sidx = qs_index[qn * SPQ + j];
            v = emb_skill[(size_t)sidx * DD + k];
            qs_s[(1 + j) * DD + k] = v;
            g_qs[(size_t)unit * 5 * DD + (1 + j) * DD + k] = v;
        }
    }
    __syncthreads();
    if (tid < 5) {
        float acc = g_scal[0];
        for (int k = 0; k < DD; k++) acc += qs_s[tid * DD + k] * g_qv[k];
        g_ql[unit * 5 + tid] = acc;
    }
    if (tid < TT) {
        const int tp = tid;
        float sc = NINF;
        if (tp < t) {
            const int qq = question[b * TT + tp];
            float acc = 0.f;
            for (int k = 0; k < DD; k++) acc += emb_question[(size_t)qq * DD + k] * qs_s[k];
            sc = acc;
        }
        scores[tp] = sc;
    }
    __syncthreads();
    // top-10 (warp 0), lax.top_k semantics: values desc, lower index first on ties.
    if (tid < 32) {
        float v0 = (tid < TT) ? scores[tid] : NINF;
        float v1 = (tid + 32 < TT) ? scores[tid + 32] : NINF;
        int idx0 = (tid < TT) ? tid : INT_MAX;
        int idx1 = (tid + 32 < TT) ? (tid + 32) : INT_MAX;
        for (int r = 0; r < RK; r++) {
            float bv; int bi;
            if (v1 > v0 || (v1 == v0 && idx1 < idx0)) { bv = v1; bi = idx1; }
            else { bv = v0; bi = idx0; }
#pragma unroll
            for (int off = 16; off; off >>= 1) {
                float ov = __shfl_xor_sync(0xffffffffu, bv, off);
                int oi = __shfl_xor_sync(0xffffffffu, bi, off);
                if (ov > bv || (ov == bv && oi < bi)) { bv = ov; bi = oi; }
            }
            if (tid == 0) {
                g_idx[unit * RK + r] = bi;
                g_sval[unit * 11 + 1 + r] = (bi < t) ? 1 : 0;
            }
            if (idx0 == bi) { v0 = NINF; idx0 = INT_MAX; }
            if (idx1 == bi) { v1 = NINF; idx1 = INT_MAX; }
        }
        if (tid == 0) g_sval[unit * 11 + 0] = 1;
    }
}

// ---------------- fus_gemm: g_et = relu(g_xf @ W_fus^T + b), 8 rows/block --
__global__ __launch_bounds__(128) void fus_gemm(const float* __restrict__ b_fusion)
{
    __shared__ __align__(16) float xs[8 * 2 * DD];
    const int r0 = blockIdx.x * 8;
    const int tid = threadIdx.x;
    const float4* src = reinterpret_cast<const float4*>(&g_xf[r0][0]);
    float4* dst = reinterpret_cast<float4*>(xs);
    for (int i = tid; i < 8 * 2 * DD / 4; i += blockDim.x) dst[i] = src[i];
    __syncthreads();
    mv_tile<8, 2 * DD, 1>(g_WT_fus, b_fusion, xs, &g_et[r0][0], tid);
}

// ---------------- pre_gemm: g_pre = g_et @ W_ih^T + b_ih + b_hh, 8 rows/block
__global__ __launch_bounds__(512) void pre_gemm(const float* __restrict__ b_ih,
                                                const float* __restrict__ b_hh)
{
    __shared__ __align__(16) float es[8 * DD];
    const int r0 = blockIdx.x * 8;
    const int tid = threadIdx.x;
    const float4* src = reinterpret_cast<const float4*>(&g_et[r0][0]);
    float4* dst = reinterpret_cast<float4*>(es);
    for (int i = tid; i < 8 * DD / 4; i += blockDim.x) dst[i] = src[i];
    __syncthreads();
    if (tid < 4 * DD) {
        float acc[8];
#pragma unroll
        for (int r = 0; r < 8; r++) acc[r] = 0.f;
        float c0 = g_WT_ih[0 * 4 * DD + tid], c1 = g_WT_ih[1 * 4 * DD + tid];
        float c2 = g_WT_ih[2 * 4 * DD + tid], c3 = g_WT_ih[3 * 4 * DD + tid];
#pragma unroll 1
        for (int k = 0; k < DD; k += 4) {
            float n0 = 0.f, n1 = 0.f, n2 = 0.f, n3 = 0.f;
            if (k + 4 < DD) {
                n0 = g_WT_ih[(k + 4) * 4 * DD + tid];
                n1 = g_WT_ih[(k + 5) * 4 * DD + tid];
                n2 = g_WT_ih[(k + 6) * 4 * DD + tid];
                n3 = g_WT_ih[(k + 7) * 4 * DD + tid];
            }
#pragma unroll
            for (int r = 0; r < 8; r++) {
                const float4 e4 = *reinterpret_cast<const float4*>(es + r * DD + k);
                acc[r] = fmaf(e4.x, c0, acc[r]);
                acc[r] = fmaf(e4.y, c1, acc[r]);
                acc[r] = fmaf(e4.z, c2, acc[r]);
                acc[r] = fmaf(e4.w, c3, acc[r]);
            }
            c0 = n0; c1 = n1; c2 = n2; c3 = n3;
        }
        const float bias = b_ih[tid] + b_hh[tid];
#pragma unroll
        for (int r = 0; r < 8; r++)
            g_pre[(size_t)(r0 + r) * 4 * DD + tid] = acc[r] + bias;
    }
}

// ---------------- Phase B: per-batch-row LSTM + attention ----------------
// 800 threads: half = tid/400, o4 = tid%400; each holds a 48/52-element
// k-slice of W_hh column o4 in registers.
__global__ __launch_bounds__(800) void phaseB_kernel(const int* __restrict__ mask,
                                                     float* __restrict__ out)
{
    __shared__ __align__(16) float h[DD];
    __shared__ __align__(16) float cst[DD];
    __shared__ __align__(16) float sh[TT * DD];
    __shared__ __align__(16) float qs_sm[2][5 * DD];
    __shared__ __align__(16) float kv_s[DD];
    __shared__ float part[800];
    __shared__ float dots[2][66];
    __shared__ int idx_s[2][RK];
    __shared__ int sval_s[2][11];
    __shared__ float ql_s[2][5];

    const int b = blockIdx.x;
    const int tid = threadIdx.x;
    const int half = tid / 400;
    const int o4 = tid - half * 400;
    const int kbase = half ? 48 : 0;

    float wreg[52];
#pragma unroll
    for (int kk = 0; kk < 52; kk++)
        wreg[kk] = g_WhhT[(kbase + kk) * 4 * DD + o4];

    for (int i = tid; i < TT * DD; i += blockDim.x) sh[i] = 0.f;
    if (tid < DD) { h[tid] = 0.f; cst[tid] = 0.f; kv_s[tid] = g_kv[tid]; }
    if (tid == 0) out[b * TT + 0] = 0.5f;
    __syncthreads();

    for (int t = 0; t < TS; t++) {
        const int row = t * BB + b;
        const int par = t & 1;

        if (tid < 500) qs_sm[par][tid] = g_qs[(size_t)row * 5 * DD + tid];
        else if (tid < 510) idx_s[par][tid - 500] = g_idx[row * RK + (tid - 500)];
        else if (tid < 521) sval_s[par][tid - 510] = g_sval[row * 11 + (tid - 510)];
        else if (tid < 526) ql_s[par][tid - 521] = g_ql[row * 5 + (tid - 521)];

        {
            float a = half ? 0.f : g_pre[(size_t)row * 4 * DD + o4];
            if (half == 0) {
#pragma unroll
                for (int g4 = 0; g4 < 12; g4++) {
                    const float4 h4 = *reinterpret_cast<const float4*>(h + 4 * g4);
                    a = fmaf(h4.x, wreg[4 * g4 + 0], a);
                    a = fmaf(h4.y, wreg[4 * g4 + 1], a);
                    a = fmaf(h4.z, wreg[4 * g4 + 2], a);
                    a = fmaf(h4.w, wreg[4 * g4 + 3], a);
                }
            } else {
#pragma unroll
                for (int g4 = 0; g4 < 13; g4++) {
                    const float4 h4 = *reinterpret_cast<const float4*>(h + 48 + 4 * g4);
                    a = fmaf(h4.x, wreg[4 * g4 + 0], a);
                    a = fmaf(h4.y, wreg[4 * g4 + 1], a);
                    a = fmaf(h4.z, wreg[4 * g4 + 2], a);
                    a = fmaf(h4.w, wreg[4 * g4 + 3], a);
                }
            }
            part[tid] = a;
        }
        __syncthreads();   // b1: gates done

        if (tid < DD) {
            const int o = tid;
            const float ai = part[o]          + part[400 + o];
            const float af = part[DD + o]     + part[400 + DD + o];
            const float ag = part[2 * DD + o] + part[400 + 2 * DD + o];
            const float ao = part[3 * DD + o] + part[400 + 3 * DD + o];
            const int m = mask[b * TT + t];
            const float ig = 1.f / (1.f + expf(-ai));
            const float fg = 1.f / (1.f + expf(-af));
            const float gg = tanhf(ag);
            const float og = 1.f / (1.f + expf(-ao));
            const float c2 = fg * cst[o] + ig * gg;
            const float h2 = og * tanhf(c2);
            const float hn = m ? h2 : h[o];
            const float cn = m ? c2 : cst[o];
            h[o] = hn; cst[o] = cn; sh[t * DD + o] = hn;
        }
        __syncthreads();   // b2: h/sh updated

        {
            const int wid = tid >> 5, lane = tid & 31;
            for (int d = wid; d < 66; d += 25) {
                const float* av;
                const float* bv;
                if (d < 55) {
                    const int q = d / 11, s = d % 11;
                    av = &qs_sm[par][q * DD];
                    bv = (s == 0) ? h : &sh[idx_s[par][s - 1] * DD];
                } else {
                    const int s = d - 55;
                    av = kv_s;
                    bv = (s == 0) ? h : &sh[idx_s[par][s - 1] * DD];
                }
                float acc = av[lane] * bv[lane] + av[lane + 32] * bv[lane + 32]
                          + av[lane + 64] * bv[lane + 64];
                if (lane < 4) acc += av[lane + 96] * bv[lane + 96];
#pragma unroll
                for (int off = 16; off; off >>= 1)
                    acc += __shfl_xor_sync(0xffffffffu, acc, off);
                if (lane == 0) dots[par][d] = acc;
            }
        }
        __syncthreads();   // b3: dots done; warp0 softmax overlaps next step

        if (tid < 32) {
            const float kbbw = g_scal[1] + g_scal[2];
            const int j0 = tid, j1 = tid + 32;
            float l0 = NINF, l1v = NINF, g0 = 0.f, g1 = 0.f;
            if (j0 < 55) {
                const int q = j0 / 11, s = j0 % 11;
                if (sval_s[par][s]) l0 = ql_s[par][q] + dots[par][55 + s] + kbbw;
                g0 = dots[par][j0];
            }
            if (j1 < 55) {
                const int q = j1 / 11, s = j1 % 11;
                if (sval_s[par][s]) l1v = ql_s[par][q] + dots[par][55 + s] + kbbw;
                g1 = dots[par][j1];
            }
            float mx = fmaxf(l0, l1v);
#pragma unroll
            for (int off = 16; off; off >>= 1)
                mx = fmaxf(mx, __shfl_xor_sync(0xffffffffu, mx, off));
            float e0 = (l0 == NINF) ? 0.f : expf(l0 - mx);
            float e1 = (l1v == NINF) ? 0.f : expf(l1v - mx);
            float es = e0 + e1;
            float ws = e0 * g0 + e1 * g1;
#pragma unroll
            for (int off = 16; off; off >>= 1) {
                es += __shfl_xor_sync(0xffffffffu, es, off);
                ws += __shfl_xor_sync(0xffffffffu, ws, off);
            }
            if (tid == 0)
                out[b * TT + t + 1] = 1.f / (1.f + expf(-(ws / es)));
        }
        // no trailing barrier: next step writes opposite-parity buffers; `part`
        // is rewritten only after b3; h changes only after next b1.
    }
}

extern "C" void kernel_launch(void* const* d_in, const int* in_sizes, int n_in,
                              void* d_out, int out_size) {
    const int* user          = (const int*)d_in[0];
    const int* question      = (const int*)d_in[1];
    const int* response      = (const int*)d_in[2];
    const int* mask          = (const int*)d_in[3];
    const int* q_neighbors   = (const int*)d_in[4];
    const int* s_neighbors   = (const int*)d_in[5];
    const int* u_neighbors   = (const int*)d_in[6];
    const int* q_neighbors_2 = (const int*)d_in[7];
    const int* qs_index      = (const int*)d_in[8];
    const float* emb_question   = (const float*)d_in[9];
    const float* emb_question_2 = (const float*)d_in[10];
    const float* emb_skill      = (const float*)d_in[11];
    const float* emb_user       = (const float*)d_in[12];
    const float* emb_response   = (const float*)d_in[13];
    const float* w1_q   = (const float*)d_in[14];
    const float* w2_q   = (const float*)d_in[15];
    const float* W_ih   = (const float*)d_in[16];
    const float* W_hh   = (const float*)d_in[17];
    const float* b_ih   = (const float*)d_in[18];
    const float* b_hh   = (const float*)d_in[19];
    const float* agg_w  = (const float*)d_in[20];
    const float* agg_b  = (const float*)d_in[21];
    const float* W_agg_last = (const float*)d_in[22];
    const float* b_agg_last = (const float*)d_in[23];
    const float* W_query = (const float*)d_in[24];
    const float* b_query = (const float*)d_in[25];
    const float* W_key   = (const float*)d_in[26];
    const float* b_key   = (const float*)d_in[27];
    const float* W_w     = (const float*)d_in[28];
    const float* b_w     = (const float*)d_in[29];
    const float* W_fusion = (const float*)d_in[30];
    const float* b_fusion = (const float*)d_in[31];
    float* out = (float*)d_out;

    prep_kernel<<<132, 256>>>(agg_w, W_agg_last, W_fusion, W_ih, W_hh,
                              W_query, b_query, W_key, b_key, W_w, b_w);
    dim3 agrid(NU, 2);
    agg_kernel<<<agrid, 256>>>(user, question, mask,
                               q_neighbors, s_neighbors, u_neighbors, q_neighbors_2,
                               emb_question, emb_question_2, emb_skill, emb_user,
                               agg_b, b_agg_last);
    mid_kernel<<<NU, 128>>>(question, response, mask, qs_index,
                            emb_question, emb_question_2, emb_skill, emb_response,
                            w1_q, w2_q);
    fus_gemm<<<NU / 8, 128>>>(b_fusion);
    pre_gemm<<<NU / 8, 512>>>(b_ih, b_hh);
    phaseB_kernel<<<BB, 800>>>(mask, out);
}

// round 14
// speedup vs baseline: 3.6165x; 1.1200x over previous
#include <cuda_runtime.h>
#include <math.h>
#include <float.h>
#include <limits.h>

#define BB 32
#define TT 50
#define DD 100
#define NBRN 6
#define SPQ 4
#define TS 49
#define RK 10
#define NINF (-INFINITY)
#define NU (TS * BB)

// ---------------- scratch (__device__ globals) ----------------
__device__ __align__(16) float g_WT_agg[3][DD * DD];   // [j][k*100+o]
__device__ __align__(16) float g_WT_last[DD * DD];     // [k*100+o]
__device__ __align__(16) float g_WT_fus[2 * DD * DD];  // [k*100+o]
__device__ __align__(16) float g_WT_ih[DD * 4 * DD];   // [k*400+o4]
__device__ __align__(16) float g_WhhT[DD * 4 * DD];    // [k*400+o4]
__device__ __align__(16) float g_qv[DD];
__device__ __align__(16) float g_kv[DD];
__device__ float g_scal[4];                            // qb, kb, bw
__device__ __align__(16) float g_eagg[2][NU][DD];
__device__ __align__(16) float g_xf[NU][2 * DD];
__device__ __align__(16) float g_pre[NU * 4 * DD];
__device__ __align__(16) float g_qs[NU * 5 * DD];
__device__ float g_ql[NU * 5];
__device__ int   g_idx[NU * RK];
__device__ int   g_sval[NU * 11];

// ---------------- prep ----------------
__global__ void prep_kernel(const float* __restrict__ agg_w,
                            const float* __restrict__ W_agg_last,
                            const float* __restrict__ W_fusion,
                            const float* __restrict__ W_ih,
                            const float* __restrict__ W_hh,
                            const float* __restrict__ W_query,
                            const float* __restrict__ b_query,
                            const float* __restrict__ W_key,
                            const float* __restrict__ b_key,
                            const float* __restrict__ W_w,
                            const float* __restrict__ b_w)
{
    int tid = blockIdx.x * blockDim.x + threadIdx.x;
    int nt = gridDim.x * blockDim.x;
    for (int i = tid; i < 3 * DD * DD; i += nt) {
        int j = i / (DD * DD), rem = i % (DD * DD);
        int o = rem / DD, k = rem % DD;
        g_WT_agg[j][k * DD + o] = agg_w[i];
    }
    for (int i = tid; i < DD * DD; i += nt) {
        int o = i / DD, k = i % DD;
        g_WT_last[k * DD + o] = W_agg_last[i];
    }
    for (int i = tid; i < DD * 2 * DD; i += nt) {
        int o = i / (2 * DD), k = i % (2 * DD);
        g_WT_fus[k * DD + o] = W_fusion[i];
    }
    for (int i = tid; i < 4 * DD * DD; i += nt) {
        int o4 = i / DD, k = i % DD;
        g_WT_ih[k * 4 * DD + o4] = W_ih[i];
    }
    for (int i = tid; i < 4 * DD * DD; i += nt) {
        int o4 = i / DD, k = i % DD;
        g_WhhT[k * 4 * DD + o4] = W_hh[i];
    }
    for (int k = tid; k < DD; k += nt) {
        float a = 0.f, bs = 0.f;
#pragma unroll 10
        for (int o = 0; o < DD; o++) {
            a  += W_query[o * DD + k] * W_w[o];
            bs += W_key[o * DD + k] * W_w[DD + o];
        }
        g_qv[k] = a;
        g_kv[k] = bs;
    }
    // qb/kb: warp-parallel reduction (was a serial single-thread LDG chain)
    if (blockIdx.x == 0 && threadIdx.x < 32) {
        const int lane = threadIdx.x;
        float qb = 0.f, kb = 0.f;
        for (int o = lane; o < DD; o += 32) {
            qb += b_query[o] * W_w[o];
            kb += b_key[o] * W_w[DD + o];
        }
#pragma unroll
        for (int off = 16; off; off >>= 1) {
            qb += __shfl_xor_sync(0xffffffffu, qb, off);
            kb += __shfl_xor_sync(0xffffffffu, kb, off);
        }
        if (lane == 0) {
            g_scal[0] = qb; g_scal[1] = kb; g_scal[2] = b_w[0];
        }
    }
}

// tiled matvec, 8-deep weight prefetch (covers ~262cyc L2 latency for TR>=8):
// sOut[r*DD+tid] = act(bias[tid] + sum_k sIn[r*KK+k]*WT[k*DD+tid])
// ACT: 0 = tanh, 1 = relu. Active only for 0 <= tid < DD. KK % 4 == 0.
template <int TR, int KK, int ACT>
__device__ __forceinline__ void mv_tile(const float* __restrict__ WT,
                                        const float* __restrict__ bias,
                                        const float* __restrict__ sIn,
                                        float* __restrict__ sOut, int tid)
{
    if (tid >= 0 && tid < DD) {
        constexpr int KM = (KK / 8) * 8;    // main-loop extent
        float acc[TR];
#pragma unroll
        for (int r = 0; r < TR; r++) acc[r] = 0.f;
        float c[8];
#pragma unroll
        for (int j = 0; j < 8; j++) c[j] = WT[j * DD + tid];
#pragma unroll 1
        for (int k = 0; k < KM; k += 8) {
            float n[8];
#pragma unroll
            for (int j = 0; j < 8; j++) {
                const int kk = k + 8 + j;
                n[j] = (kk < KK) ? WT[kk * DD + tid] : 0.f;
            }
#pragma unroll
            for (int r = 0; r < TR; r++) {
                const float4 sa = *reinterpret_cast<const float4*>(sIn + r * KK + k);
                const float4 sb = *reinterpret_cast<const float4*>(sIn + r * KK + k + 4);
                acc[r] = fmaf(sa.x, c[0], acc[r]);
                acc[r] = fmaf(sa.y, c[1], acc[r]);
                acc[r] = fmaf(sa.z, c[2], acc[r]);
                acc[r] = fmaf(sa.w, c[3], acc[r]);
                acc[r] = fmaf(sb.x, c[4], acc[r]);
                acc[r] = fmaf(sb.y, c[5], acc[r]);
                acc[r] = fmaf(sb.z, c[6], acc[r]);
                acc[r] = fmaf(sb.w, c[7], acc[r]);
            }
#pragma unroll
            for (int j = 0; j < 8; j++) c[j] = n[j];
        }
        if (KK > KM) {   // tail of 4 (c[0..3] hold k=KM..KM+3)
#pragma unroll
            for (int r = 0; r < TR; r++) {
                const float4 sa = *reinterpret_cast<const float4*>(sIn + r * KK + KM);
                acc[r] = fmaf(sa.x, c[0], acc[r]);
                acc[r] = fmaf(sa.y, c[1], acc[r]);
                acc[r] = fmaf(sa.z, c[2], acc[r]);
                acc[r] = fmaf(sa.w, c[3], acc[r]);
            }
        }
        float bv = bias[tid];
#pragma unroll
        for (int r = 0; r < TR; r++) {
            float v = acc[r] + bv;
            sOut[r * DD + tid] = (ACT == 0) ? tanhf(v) : fmaxf(v, 0.f);
        }
    }
}

// ---------------- agg: one (side, t, b) per block, 256 threads ----------------
__global__ __launch_bounds__(256) void agg_kernel(
    const int* __restrict__ user, const int* __restrict__ question,
    const int* __restrict__ mask,
    const int* __restrict__ q_neighbors, const int* __restrict__ s_neighbors,
    const int* __restrict__ u_neighbors, const int* __restrict__ q_neighbors_2,
    const float* __restrict__ emb_question, const float* __restrict__ emb_question_2,
    const float* __restrict__ emb_skill, const float* __restrict__ emb_user,
    const float* __restrict__ agg_b, const float* __restrict__ b_agg_last)
{
    __shared__ int l1[NBRN];
    __shared__ int l2[36];
    __shared__ int l3[216];
    __shared__ __align__(16) float s2[36 * DD];
    __shared__ __align__(16) float e2[36 * DD];
    __shared__ __align__(16) float s1[6 * DD];
    __shared__ __align__(16) float e1[6 * DD];
    __shared__ __align__(16) float s0[DD];
    __shared__ __align__(16) float e0v[DD];

    const int unit = blockIdx.x;
    const int side = blockIdx.y;
    const int t = unit / BB;
    const int b = unit % BB;
    const int tid = threadIdx.x;
    const int lt = tid;
    const int ut = tid - 128;
    const float inv6 = 1.0f / 6.0f;

    if (!mask[b * TT + t]) return;

    int node;
    const int *tabA, *tabB;
    const float *embX, *embY;
    if (side == 0) {
        node = question[b * TT + t];
        tabA = q_neighbors; tabB = s_neighbors;
        embX = emb_question; embY = emb_skill;
    } else {
        node = user[b * TT + t];
        tabA = u_neighbors; tabB = q_neighbors_2;
        embX = emb_user; embY = emb_question_2;
    }
    if (tid < NBRN) l1[tid] = tabA[node * NBRN + tid];
    __syncthreads();
    if (tid < 36) l2[tid] = tabB[l1[tid / 6] * NBRN + tid % 6];
    __syncthreads();
    if (tid < 216) l3[tid] = tabA[l2[tid / 6] * NBRN + tid % 6];
    __syncthreads();

    for (int idx = tid; idx < 3600; idx += 256) {
        const int p = idx / DD, k = idx - p * DD;
        float mm = 0.f;
#pragma unroll
        for (int l = 0; l < 6; l++) mm += embY[(size_t)l3[p * 6 + l] * DD + k];
        s2[p * DD + k] = embX[(size_t)l2[p] * DD + k] + mm * inv6;
    }
    if (tid < DD) {
        const int k = lt;
        float mm = 0.f;
#pragma unroll
        for (int i = 0; i < 6; i++) mm += embY[(size_t)l1[i] * DD + k];
        s0[k] = embX[(size_t)node * DD + k] + mm * inv6;
        for (int i = 0; i < 3; i++) {
            float m2 = 0.f;
#pragma unroll
            for (int j = 0; j < 6; j++) m2 += embX[(size_t)l2[i * 6 + j] * DD + k];
            s1[i * DD + k] = embY[(size_t)l1[i] * DD + k] + m2 * inv6;
        }
    } else if (ut >= 0 && ut < DD) {
        const int k = ut;
        for (int i = 3; i < 6; i++) {
            float m2 = 0.f;
#pragma unroll
            for (int j = 0; j < 6; j++) m2 += embX[(size_t)l2[i * 6 + j] * DD + k];
            s1[i * DD + k] = embY[(size_t)l1[i] * DD + k] + m2 * inv6;
        }
    }
    __syncthreads();

    // sweep i=0: halves run G2a+G1 | G2b+G0 concurrently
    if (tid < 128) {
        mv_tile<18, DD, 0>(g_WT_agg[2], agg_b + 2 * DD, s2, e2, lt);
        mv_tile<6, DD, 0>(g_WT_agg[1], agg_b + 1 * DD, s1, e1, lt);
    } else {
        mv_tile<18, DD, 0>(g_WT_agg[2], agg_b + 2 * DD, s2 + 18 * DD, e2 + 18 * DD, ut);
        mv_tile<1, DD, 0>(g_WT_agg[0], agg_b + 0 * DD, s0, e0v, ut);
    }
    __syncthreads();

    if (tid < DD) {
        const int k = lt;
        float nm[6];
        for (int i = 0; i < 6; i++) {
            float mm = 0.f;
#pragma unroll
            for (int j = 0; j < 6; j++) mm += e2[(i * 6 + j) * DD + k];
            nm[i] = e1[i * DD + k] + mm * inv6;
        }
        for (int i = 0; i < 6; i++) s1[i * DD + k] = nm[i];
    } else if (ut >= 0 && ut < DD) {
        const int k = ut;
        float mm = 0.f;
#pragma unroll
        for (int i = 0; i < 6; i++) mm += e1[i * DD + k];
        s0[k] = e0v[k] + mm * inv6;
    }
    __syncthreads();

    // sweep i=1: G1 | G0 concurrently
    if (tid < 128) {
        mv_tile<6, DD, 0>(g_WT_agg[1], agg_b + 1 * DD, s1, e1, lt);
    } else {
        mv_tile<1, DD, 0>(g_WT_agg[0], agg_b + 0 * DD, s0, e0v, ut);
    }
    __syncthreads();

    if (tid < DD) {
        const int k = lt;
        float mm = 0.f;
#pragma unroll
        for (int i = 0; i < 6; i++) mm += e1[i * DD + k];
        s0[k] = e0v[k] + mm * inv6;
    }
    __syncthreads();
    mv_tile<1, DD, 0>(g_WT_agg[0], agg_b + 0 * DD, s0, e0v, lt);
    __syncthreads();
    mv_tile<1, DD, 0>(g_WT_last, b_agg_last, e0v, s0, lt);
    if (tid < DD) g_eagg[side][unit][tid] = s0[tid];
}

// ---------------- mid: ehat/xf + attention precompute + top-k ----------------
__global__ __launch_bounds__(128) void mid_kernel(
    const int* __restrict__ question, const int* __restrict__ response,
    const int* __restrict__ mask, const int* __restrict__ qs_index,
    const float* __restrict__ emb_question, const float* __restrict__ emb_question_2,
    const float* __restrict__ emb_skill, const float* __restrict__ emb_response,
    const float* __restrict__ w1_q, const float* __restrict__ w2_q)
{
    __shared__ __align__(16) float qs_s[5 * DD];
    __shared__ float scores[TT];

    const int unit = blockIdx.x;
    const int t = unit / BB;
    const int b = unit % BB;
    const int tid = threadIdx.x;

    const int q_t = question[b * TT + t];
    const int r_t = response[b * TT + t];
    const int m = mask[b * TT + t];
    const float w1 = w1_q[0], w2 = w2_q[0];

    if (tid < DD) {
        float eh;
        if (m) eh = w1 * g_eagg[0][unit][tid] + w2 * g_eagg[1][unit][tid];
        else   eh = w1 * emb_question[(size_t)q_t * DD + tid]
                  + w2 * emb_question_2[(size_t)q_t * DD + tid];
        g_xf[unit][tid] = eh;
        g_xf[unit][DD + tid] = emb_response[r_t * DD + tid];
    }

    const int qn = question[b * TT + t + 1];
    if (tid < DD) {
        const int k = tid;
        float v = emb_question[(size_t)qn * DD + k];
        qs_s[k] = v;
        g_qs[(size_t)unit * 5 * DD + k] = v;
#pragma unroll
        for (int j = 0; j < 4; j++) {
            int sidx = qs_index[qn * SPQ + j];
            v = emb_skill[(size_t)sidx * DD + k];
            qs_s[(1 + j) * DD + k] = v;
            g_qs[(size_t)unit * 5 * DD + (1 + j) * DD + k] = v;
        }
    }
    __syncthreads();
    if (tid < 5) {
        float acc = g_scal[0];
        for (int k = 0; k < DD; k++) acc += qs_s[tid * DD + k] * g_qv[k];
        g_ql[unit * 5 + tid] = acc;
    }
    if (tid < TT) {
        const int tp = tid;
        float sc = NINF;
        if (tp < t) {
            const int qq = question[b * TT + tp];
            float acc = 0.f;
            for (int k = 0; k < DD; k++) acc += emb_question[(size_t)qq * DD + k] * qs_s[k];
            sc = acc;
        }
        scores[tp] = sc;
    }
    __syncthreads();
    // top-10 (warp 0), lax.top_k semantics: values desc, lower index first on ties.
    if (tid < 32) {
        float v0 = (tid < TT) ? scores[tid] : NINF;
        float v1 = (tid + 32 < TT) ? scores[tid + 32] : NINF;
        int idx0 = (tid < TT) ? tid : INT_MAX;
        int idx1 = (tid + 32 < TT) ? (tid + 32) : INT_MAX;
        for (int r = 0; r < RK; r++) {
            float bv; int bi;
            if (v1 > v0 || (v1 == v0 && idx1 < idx0)) { bv = v1; bi = idx1; }
            else { bv = v0; bi = idx0; }
#pragma unroll
            for (int off = 16; off; off >>= 1) {
                float ov = __shfl_xor_sync(0xffffffffu, bv, off);
                int oi = __shfl_xor_sync(0xffffffffu, bi, off);
                if (ov > bv || (ov == bv && oi < bi)) { bv = ov; bi = oi; }
            }
            if (tid == 0) {
                g_idx[unit * RK + r] = bi;
                g_sval[unit * 11 + 1 + r] = (bi < t) ? 1 : 0;
            }
            if (idx0 == bi) { v0 = NINF; idx0 = INT_MAX; }
            if (idx1 == bi) { v1 = NINF; idx1 = INT_MAX; }
        }
        if (tid == 0) g_sval[unit * 11 + 0] = 1;
    }
}

// ---------------- fp_gemm: fusion + pre in one kernel, 8 rows/block ----------
// fus: 4-way K-split (kg = tid/128 handles k-groups g%4==kg), partials in smem.
// pre: o4 = tid (<400) consumes es directly from smem.
__global__ __launch_bounds__(512) void fp_gemm(const float* __restrict__ b_fusion,
                                               const float* __restrict__ b_ih,
                                               const float* __restrict__ b_hh)
{
    __shared__ __align__(16) float xs[8 * 2 * DD];
    __shared__ __align__(16) float ps[4][8][DD];
    __shared__ __align__(16) float es[8 * DD];
    const int r0 = blockIdx.x * 8;
    const int tid = threadIdx.x;
    const int kg = tid >> 7;          // 0..3
    const int o  = tid & 127;         // lane within group

    {
        const float4* src = reinterpret_cast<const float4*>(&g_xf[r0][0]);
        float4* dst = reinterpret_cast<float4*>(xs);
        for (int i = tid; i < 8 * 2 * DD / 4; i += 512) dst[i] = src[i];
    }
    __syncthreads();

    // fus partial sums: k-groups of 4, group g handled by kg == g%4
    if (o < DD) {
        float acc[8];
#pragma unroll
        for (int r = 0; r < 8; r++) acc[r] = 0.f;
#pragma unroll
        for (int j = 0; j < 13; j++) {
            const int k = (kg + 4 * j) * 4;
            if (k < 2 * DD) {
                const float w0 = g_WT_fus[(k + 0) * DD + o];
                const float w1 = g_WT_fus[(k + 1) * DD + o];
                const float w2 = g_WT_fus[(k + 2) * DD + o];
                const float w3 = g_WT_fus[(k + 3) * DD + o];
#pragma unroll
                for (int r = 0; r < 8; r++) {
                    const float4 s4 = *reinterpret_cast<const float4*>(xs + r * 2 * DD + k);
                    acc[r] = fmaf(s4.x, w0, acc[r]);
                    acc[r] = fmaf(s4.y, w1, acc[r]);
                    acc[r] = fmaf(s4.z, w2, acc[r]);
                    acc[r] = fmaf(s4.w, w3, acc[r]);
                }
            }
        }
#pragma unroll
        for (int r = 0; r < 8; r++) ps[kg][r][o] = acc[r];
    }
    __syncthreads();

    // reduce + bias + relu -> es (800 outputs, 2 per thread for tid<400)
    if (tid < 400) {
#pragma unroll
        for (int p = tid; p < 800; p += 400) {
            const int r = p / DD, oo = p - r * DD;
            float v = ps[0][r][oo] + ps[1][r][oo] + ps[2][r][oo] + ps[3][r][oo]
                    + b_fusion[oo];
            es[r * DD + oo] = fmaxf(v, 0.f);
        }
    }
    __syncthreads();

    // pre: 400 output columns, K=100, 8-deep weight prefetch
    if (tid < 4 * DD) {
        float acc[8];
#pragma unroll
        for (int r = 0; r < 8; r++) acc[r] = 0.f;
        float c[8];
#pragma unroll
        for (int j = 0; j < 8; j++) c[j] = g_WT_ih[j * 4 * DD + tid];
#pragma unroll 1
        for (int k = 0; k < 96; k += 8) {
            float n[8];
#pragma unroll
            for (int j = 0; j < 8; j++) {
                const int kk = k + 8 + j;
                n[j] = (kk < DD) ? g_WT_ih[kk * 4 * DD + tid] : 0.f;
            }
#pragma unroll
            for (int r = 0; r < 8; r++) {
                const float4 sa = *reinterpret_cast<const float4*>(es + r * DD + k);
                const float4 sb = *reinterpret_cast<const float4*>(es + r * DD + k + 4);
                acc[r] = fmaf(sa.x, c[0], acc[r]);
                acc[r] = fmaf(sa.y, c[1], acc[r]);
                acc[r] = fmaf(sa.z, c[2], acc[r]);
                acc[r] = fmaf(sa.w, c[3], acc[r]);
                acc[r] = fmaf(sb.x, c[4], acc[r]);
                acc[r] = fmaf(sb.y, c[5], acc[r]);
                acc[r] = fmaf(sb.z, c[6], acc[r]);
                acc[r] = fmaf(sb.w, c[7], acc[r]);
            }
#pragma unroll
            for (int j = 0; j < 8; j++) c[j] = n[j];
        }
        // tail k=96..99 (c[0..3] valid)
#pragma unroll
        for (int r = 0; r < 8; r++) {
            const float4 sa = *reinterpret_cast<const float4*>(es + r * DD + 96);
            acc[r] = fmaf(sa.x, c[0], acc[r]);
            acc[r] = fmaf(sa.y, c[1], acc[r]);
            acc[r] = fmaf(sa.z, c[2], acc[r]);
            acc[r] = fmaf(sa.w, c[3], acc[r]);
        }
        const float bias = b_ih[tid] + b_hh[tid];
#pragma unroll
        for (int r = 0; r < 8; r++)
            g_pre[(size_t)(r0 + r) * 4 * DD + tid] = acc[r] + bias;
    }
}

// ---------------- Phase B: per-batch-row LSTM + attention ----------------
__global__ __launch_bounds__(800) void phaseB_kernel(const int* __restrict__ mask,
                                                     float* __restrict__ out)
{
    __shared__ __align__(16) float h[DD];
    __shared__ __align__(16) float cst[DD];
    __shared__ __align__(16) float sh[TT * DD];
    __shared__ __align__(16) float qs_sm[2][5 * DD];
    __shared__ __align__(16) float kv_s[DD];
    __shared__ float part[800];
    __shared__ float dots[2][66];
    __shared__ int idx_s[2][RK];
    __shared__ int sval_s[2][11];
    __shared__ float ql_s[2][5];

    const int b = blockIdx.x;
    const int tid = threadIdx.x;
    const int half = tid / 400;
    const int o4 = tid - half * 400;
    const int kbase = half ? 48 : 0;

    float wreg[52];
#pragma unroll
    for (int kk = 0; kk < 52; kk++)
        wreg[kk] = g_WhhT[(kbase + kk) * 4 * DD + o4];

    for (int i = tid; i < TT * DD; i += blockDim.x) sh[i] = 0.f;
    if (tid < DD) { h[tid] = 0.f; cst[tid] = 0.f; kv_s[tid] = g_kv[tid]; }
    if (tid == 0) out[b * TT + 0] = 0.5f;
    __syncthreads();

    for (int t = 0; t < TS; t++) {
        const int row = t * BB + b;
        const int par = t & 1;

        if (tid < 500) qs_sm[par][tid] = g_qs[(size_t)row * 5 * DD + tid];
        else if (tid < 510) idx_s[par][tid - 500] = g_idx[row * RK + (tid - 500)];
        else if (tid < 521) sval_s[par][tid - 510] = g_sval[row * 11 + (tid - 510)];
        else if (tid < 526) ql_s[par][tid - 521] = g_ql[row * 5 + (tid - 521)];

        {
            float a = half ? 0.f : g_pre[(size_t)row * 4 * DD + o4];
            if (half == 0) {
#pragma unroll
                for (int g4 = 0; g4 < 12; g4++) {
                    const float4 h4 = *reinterpret_cast<const float4*>(h + 4 * g4);
                    a = fmaf(h4.x, wreg[4 * g4 + 0], a);
                    a = fmaf(h4.y, wreg[4 * g4 + 1], a);
                    a = fmaf(h4.z, wreg[4 * g4 + 2], a);
                    a = fmaf(h4.w, wreg[4 * g4 + 3], a);
                }
            } else {
#pragma unroll
                for (int g4 = 0; g4 < 13; g4++) {
                    const float4 h4 = *reinterpret_cast<const float4*>(h + 48 + 4 * g4);
                    a = fmaf(h4.x, wreg[4 * g4 + 0], a);
                    a = fmaf(h4.y, wreg[4 * g4 + 1], a);
                    a = fmaf(h4.z, wreg[4 * g4 + 2], a);
                    a = fmaf(h4.w, wreg[4 * g4 + 3], a);
                }
            }
            part[tid] = a;
        }
        __syncthreads();   // b1: gates done

        if (tid < DD) {
            const int o = tid;
            const float ai = part[o]          + part[400 + o];
            const float af = part[DD + o]     + part[400 + DD + o];
            const float ag = part[2 * DD + o] + part[400 + 2 * DD + o];
            const float ao = part[3 * DD + o] + part[400 + 3 * DD + o];
            const int m = mask[b * TT + t];
            const float ig = 1.f / (1.f + expf(-ai));
            const float fg = 1.f / (1.f + expf(-af));
            const float gg = tanhf(ag);
            const float og = 1.f / (1.f + expf(-ao));
            const float c2 = fg * cst[o] + ig * gg;
            const float h2 = og * tanhf(c2);
            const float hn = m ? h2 : h[o];
            const float cn = m ? c2 : cst[o];
            h[o] = hn; cst[o] = cn; sh[t * DD + o] = hn;
        }
        __syncthreads();   // b2: h/sh updated

        {
            const int wid = tid >> 5, lane = tid & 31;
            for (int d = wid; d < 66; d += 25) {
                const float* av;
                const float* bv;
                if (d < 55) {
                    const int q = d / 11, s = d % 11;
                    av = &qs_sm[par][q * DD];
                    bv = (s == 0) ? h : &sh[idx_s[par][s - 1] * DD];
                } else {
                    const int s = d - 55;
                    av = kv_s;
                    bv = (s == 0) ? h : &sh[idx_s[par][s - 1] * DD];
                }
                float acc = av[lane] * bv[lane] + av[lane + 32] * bv[lane + 32]
                          + av[lane + 64] * bv[lane + 64];
                if (lane < 4) acc += av[lane + 96] * bv[lane + 96];
#pragma unroll
                for (int off = 16; off; off >>= 1)
                    acc += __shfl_xor_sync(0xffffffffu, acc, off);
                if (lane == 0) dots[par][d] = acc;
            }
        }
        __syncthreads();   // b3: dots done; warp0 softmax overlaps next step

        if (tid < 32) {
            const float kbbw = g_scal[1] + g_scal[2];
            const int j0 = tid, j1 = tid + 32;
            float l0 = NINF, l1v = NINF, g0 = 0.f, g1 = 0.f;
            if (j0 < 55) {
                const int q = j0 / 11, s = j0 % 11;
                if (sval_s[par][s]) l0 = ql_s[par][q] + dots[par][55 + s] + kbbw;
                g0 = dots[par][j0];
            }
            if (j1 < 55) {
                const int q = j1 / 11, s = j1 % 11;
                if (sval_s[par][s]) l1v = ql_s[par][q] + dots[par][55 + s] + kbbw;
                g1 = dots[par][j1];
            }
            float mx = fmaxf(l0, l1v);
#pragma unroll
            for (int off = 16; off; off >>= 1)
                mx = fmaxf(mx, __shfl_xor_sync(0xffffffffu, mx, off));
            float e0 = (l0 == NINF) ? 0.f : expf(l0 - mx);
            float e1 = (l1v == NINF) ? 0.f : expf(l1v - mx);
            float es = e0 + e1;
            float ws = e0 * g0 + e1 * g1;
#pragma unroll
            for (int off = 16; off; off >>= 1) {
                es += __shfl_xor_sync(0xffffffffu, es, off);
                ws += __shfl_xor_sync(0xffffffffu, ws, off);
            }
            if (tid == 0)
                out[b * TT + t + 1] = 1.f / (1.f + expf(-(ws / es)));
        }
        // no trailing barrier: next step writes opposite-parity buffers.
    }
}

extern "C" void kernel_launch(void* const* d_in, const int* in_sizes, int n_in,
                              void* d_out, int out_size) {
    const int* user          = (const int*)d_in[0];
    const int* question      = (const int*)d_in[1];
    const int* response      = (const int*)d_in[2];
    const int* mask          = (const int*)d_in[3];
    const int* q_neighbors   = (const int*)d_in[4];
    const int* s_neighbors   = (const int*)d_in[5];
    const int* u_neighbors   = (const int*)d_in[6];
    const int* q_neighbors_2 = (const int*)d_in[7];
    const int* qs_index      = (const int*)d_in[8];
    const float* emb_question   = (const float*)d_in[9];
    const float* emb_question_2 = (const float*)d_in[10];
    const float* emb_skill      = (const float*)d_in[11];
    const float* emb_user       = (const float*)d_in[12];
    const float* emb_response   = (const float*)d_in[13];
    const float* w1_q   = (const float*)d_in[14];
    const float* w2_q   = (const float*)d_in[15];
    const float* W_ih   = (const float*)d_in[16];
    const float* W_hh   = (const float*)d_in[17];
    const float* b_ih   = (const float*)d_in[18];
    const float* b_hh   = (const float*)d_in[19];
    const float* agg_w  = (const float*)d_in[20];
    const float* agg_b  = (const float*)d_in[21];
    const float* W_agg_last = (const float*)d_in[22];
    const float* b_agg_last = (const float*)d_in[23];
    const float* W_query = (const float*)d_in[24];
    const float* b_query = (const float*)d_in[25];
    const float* W_key   = (const float*)d_in[26];
    const float* b_key   = (const float*)d_in[27];
    const float* W_w     = (const float*)d_in[28];
    const float* b_w     = (const float*)d_in[29];
    const float* W_fusion = (const float*)d_in[30];
    const float* b_fusion = (const float*)d_in[31];
    float* out = (float*)d_out;

    prep_kernel<<<132, 256>>>(agg_w, W_agg_last, W_fusion, W_ih, W_hh,
                              W_query, b_query, W_key, b_key, W_w, b_w);
    dim3 agrid(NU, 2);
    agg_kernel<<<agrid, 256>>>(user, question, mask,
                               q_neighbors, s_neighbors, u_neighbors, q_neighbors_2,
                               emb_question, emb_question_2, emb_skill, emb_user,
                               agg_b, b_agg_last);
    mid_kernel<<<NU, 128>>>(question, response, mask, qs_index,
                            emb_question, emb_question_2, emb_skill, emb_response,
                            w1_q, w2_q);
    fp_gemm<<<NU / 8, 512>>>(b_fusion, b_ih, b_hh);
    phaseB_kernel<<<BB, 800>>>(mask, out);
}